// round 11
// baseline (speedup 1.0000x reference)
#include <cuda_runtime.h>
#include <cstdint>

#define Bsz 128
#define Tt 256
#define Hh 200
#define IN1 400
#define BT (Bsz*Tt)
#define NCLASS 2
#define G16 1600

// ---------------- device scratch (static, no allocation) ----------------
__device__ __align__(16) float d_x0[BT*400];        // embeddings, tf32, natural layout
__device__ __align__(16) float d_x1[BT*400];        // layer0 output (tf32, natural)
__device__ __align__(16) float d_rnn[BT*400];       // layer1 output (fp32, natural)
__device__ __align__(16) float d_g[(size_t)BT*G16]; // gates: [bt][fwd 800 | bwd 800]
__device__ __align__(16) float d_h[2][2][Bsz*Hh];   // [dir][buf][b*200+u] k-pair-packed
__device__ __align__(16) float d_hfin[2][Bsz*Hh];   // natural
__device__ __align__(16) float d_att[3][Bsz*IN1];
__device__ __align__(16) float d_wcat[2][G16*400];  // padded tf32 W_ih, k pair-packed
__device__ __align__(16) float d_bcat[2][G16];
__device__ __align__(16) float d_mt[Tt*Bsz];        // keep-mask transposed [t][b]
__device__ unsigned d_flags[512];                   // 16 groups x 32 per-producer flags

// ---------------- helpers ----------------
__device__ __forceinline__ float tanh_(float x) {
    float r;
    asm("tanh.approx.f32 %0, %1;" : "=f"(r) : "f"(x));
    return r;
}
__device__ __forceinline__ float sig_(float x) {
    return fmaf(tanh_(0.5f * x), 0.5f, 0.5f);
}
__device__ __forceinline__ float to_tf32(float x) {
    float r;
    asm("cvt.rna.tf32.f32 %0, %1;" : "=f"(r) : "f"(x));
    return r;
}
__device__ __forceinline__ void mma_tf32(float* d, const uint32_t* a, const uint32_t* b) {
    asm volatile(
        "mma.sync.aligned.m16n8k8.row.col.f32.tf32.tf32.f32 "
        "{%0,%1,%2,%3}, {%4,%5,%6,%7}, {%8,%9}, {%0,%1,%2,%3};"
        : "+f"(d[0]), "+f"(d[1]), "+f"(d[2]), "+f"(d[3])
        : "r"(a[0]), "r"(a[1]), "r"(a[2]), "r"(a[3]), "r"(b[0]), "r"(b[1]));
}
__device__ __forceinline__ void cp16(uint32_t saddr, const void* gaddr) {
    asm volatile("cp.async.cg.shared.global [%0], [%1], 16;" :: "r"(saddr), "l"(gaddr));
}
__device__ __forceinline__ unsigned ld_acq(const unsigned* p) {
    unsigned v;
    asm volatile("ld.acquire.gpu.global.u32 %0, [%1];" : "=r"(v) : "l"(p) : "memory");
    return v;
}
__device__ __forceinline__ void st_rel(unsigned* p, unsigned v) {
    asm volatile("st.release.gpu.global.u32 [%0], %1;" :: "l"(p), "r"(v) : "memory");
}

// ---------------- fused embed + prep ----------------------------------------
// d_x0 natural layout; wcat k-pair-packed: packed position p holds source
// k = k0*8 + tg + 4c where p = k0*8 + tg*2 + c.
__global__ void embedprep_kernel(const int* __restrict__ words, const int* __restrict__ pos,
                                 const int* __restrict__ ner,
                                 const float* __restrict__ emb_w, const float* __restrict__ pos_w,
                                 const float* __restrict__ ner_w,
                                 const float* __restrict__ wf0, const float* __restrict__ wb0,
                                 const float* __restrict__ bf0, const float* __restrict__ bb0,
                                 const float* __restrict__ wf1, const float* __restrict__ wb1,
                                 const float* __restrict__ bf1, const float* __restrict__ bb1,
                                 const int* __restrict__ masks) {
    int i = blockIdx.x * blockDim.x + threadIdx.x;
    if (i < BT * 400) {
        int c = i % 400, bt = i / 400;
        float v = 0.f;
        if (c < 300)        v = emb_w[(size_t)words[bt] * 300 + c];
        else if (c < 330)   v = pos_w[(size_t)pos[bt] * 30 + (c - 300)];
        else if (c < 360)   v = ner_w[(size_t)ner[bt] * 30 + (c - 330)];
        d_x0[i] = to_tf32(v);
    }
    if (i < G16 * 400) {
        int n = i / 400, p = i % 400;
        int k0 = p >> 3, r = p & 7, tg = r >> 1, c = r & 1;
        int k = k0 * 8 + tg + 4 * c;
        int nn = (n < 800) ? n : n - 800;
        float v0 = 0.f, v1 = 0.f;
        if (k < 360) {
            const float* W = (n < 800) ? wf0 : wb0;
            v0 = to_tf32(W[(size_t)nn * 360 + k]);
        }
        {
            const float* W = (n < 800) ? wf1 : wb1;
            v1 = to_tf32(W[(size_t)nn * 400 + k]);
        }
        d_wcat[0][i] = v0;
        d_wcat[1][i] = v1;
    }
    if (i < G16) {
        d_bcat[0][i] = (i < 800) ? bf0[i] : bb0[i - 800];
        d_bcat[1][i] = (i < 800) ? bf1[i] : bb1[i - 800];
    }
    if (i < Tt * Bsz) {
        int t = i / Bsz, b = i % Bsz;
        d_mt[i] = (masks[b * Tt + t] == 0) ? 1.f : 0.f;
    }
    if (i < 2 * 2 * Bsz * Hh) ((float*)d_h)[i] = 0.f;
    if (i < 512) d_flags[i] = 0;
}

// ---------------- init between layers: reset h + flags ----------------
__global__ void init2_kernel() {
    int i = blockIdx.x * blockDim.x + threadIdx.x;
    if (i < 2 * 2 * Bsz * Hh) ((float*)d_h)[i] = 0.f;
    if (i < 512) d_flags[i] = 0;
}

// ---------------- TF32 GEMM: d_g[32768,1600] = A[32768,400] @ Wcat^T + bias -
// BM=128, BN=160, BK=40, 3-stage cp.async ring. A natural (scalar LDS),
// B k-pair-packed (LDS.64). R9-proven mainloop.
#define GSTG 12672   // floats per stage: A 128*44 + B 160*44

__global__ __launch_bounds__(512, 1)
void gemm_tf32(int asel, int layer) {
    extern __shared__ float smg[];
    const float* A = asel ? d_x1 : d_x0;
    const float* Wc = d_wcat[layer];
    const float* bc = d_bcat[layer];

    const int tid = threadIdx.x;
    const int lane = tid & 31, w = tid >> 5;
    const int wm = w & 3, wn = w >> 2;
    const int g = lane >> 2, tg = lane & 3;
    const int m0 = blockIdx.y * 128, n0 = blockIdx.x * 160;

    const uint32_t sbase = (uint32_t)__cvta_generic_to_shared(smg);

    float acc[2][5][4];
#pragma unroll
    for (int i = 0; i < 2; i++)
#pragma unroll
        for (int j = 0; j < 5; j++)
#pragma unroll
            for (int r = 0; r < 4; r++) acc[i][j][r] = 0.f;

#define STAGE(IT, S) do {                                                      \
        int k0 = (IT) * 40;                                                    \
        uint32_t aB = sbase + (uint32_t)((S) * GSTG) * 4;                      \
        uint32_t bB = aB + 5632u * 4u;                                         \
        for (int i = tid; i < 1280; i += 512) {                                \
            int row = i / 10, c4 = (i % 10) * 4;                               \
            cp16(aB + (uint32_t)(row * 44 + c4) * 4,                           \
                 A + (size_t)(m0 + row) * 400 + k0 + c4);                      \
        }                                                                      \
        for (int i = tid; i < 1600; i += 512) {                                \
            int row = i / 10, c4 = (i % 10) * 4;                               \
            cp16(bB + (uint32_t)(row * 44 + c4) * 4,                           \
                 Wc + (size_t)(n0 + row) * 400 + k0 + c4);                     \
        }                                                                      \
        asm volatile("cp.async.commit_group;");                                \
    } while (0)

    STAGE(0, 0);
    STAGE(1, 1);

    for (int it = 0; it < 10; it++) {
        asm volatile("cp.async.wait_group 1;");
        __syncthreads();
        if (it + 2 < 10) STAGE(it + 2, (it + 2) % 3);

        const float* As = smg + (it % 3) * GSTG;
        const float* Bs = As + 5632;
#pragma unroll
        for (int ks = 0; ks < 5; ks++) {
            const int kb = ks * 8;
            uint32_t afr[2][4];
#pragma unroll
            for (int mi = 0; mi < 2; mi++) {
                int m = wm * 32 + mi * 16 + g;
                afr[mi][0] = __float_as_uint(As[m * 44 + kb + tg]);
                afr[mi][1] = __float_as_uint(As[(m + 8) * 44 + kb + tg]);
                afr[mi][2] = __float_as_uint(As[m * 44 + kb + tg + 4]);
                afr[mi][3] = __float_as_uint(As[(m + 8) * 44 + kb + tg + 4]);
            }
            uint32_t bfr[5][2];
#pragma unroll
            for (int nj = 0; nj < 5; nj++) {
                int n = wn * 40 + nj * 8 + g;
                float2 bp = *(const float2*)&Bs[n * 44 + kb + tg * 2];  // pair-packed
                bfr[nj][0] = __float_as_uint(bp.x);
                bfr[nj][1] = __float_as_uint(bp.y);
            }
#pragma unroll
            for (int mi = 0; mi < 2; mi++)
#pragma unroll
                for (int nj = 0; nj < 5; nj++)
                    mma_tf32(acc[mi][nj], afr[mi], bfr[nj]);
        }
    }
#undef STAGE

#pragma unroll
    for (int mi = 0; mi < 2; mi++) {
        int mrow = m0 + wm * 32 + mi * 16 + g;
#pragma unroll
        for (int nj = 0; nj < 5; nj++) {
            int ncol = n0 + wn * 40 + nj * 8 + 2 * tg;
            float bx = bc[ncol], by = bc[ncol + 1];
            *(float2*)(d_g + (size_t)mrow * G16 + ncol) =
                make_float2(acc[mi][nj][0] + bx, acc[mi][nj][1] + by);
            *(float2*)(d_g + (size_t)(mrow + 8) * G16 + ncol) =
                make_float2(acc[mi][nj][2] + bx, acc[mi][nj][3] + by);
        }
    }
}

// ---------------- persistent tensor-core bidirectional LSTM ----------------
// 100 blocks = 2 dir x 2 batch-halves x 25 u-slices. 128 thr (4 warps).
// Sync: per-producer release FLAGS (one st.release per warp per step,
// distinct addresses -> no L2-atomic same-address serialization); consumer
// polls 25 coalesced flags with ld.acquire + __all_sync, then bulk-stages.
#define NDB 25

__global__ __launch_bounds__(128, 1)
void lstm_layer(const float* __restrict__ Whhf, const float* __restrict__ Whhb, int layer) {
    extern __shared__ float sm[];
    float* hs = sm;            // [64][212] = 13568 floats
    float* Wp = sm + 13568;    // [32][206] = 6592 floats

    const int tid = threadIdx.x;
    const int lane = tid & 31, w = tid >> 5;   // w in 0..3
    const int bx = blockIdx.x;
    const int dir = bx / (2 * NDB);
    const int mh  = (bx / NDB) & 1;
    const int us  = bx % NDB;
    const int u0  = us * 8;
    const float* Whh = dir ? Whhb : Whhf;
    float* out = layer ? d_rnn : d_x1;
    float* hbuf0 = d_h[dir][0];
    float* hbuf1 = d_h[dir][1];

    // pack W_hh slice, tf32, pair-packed for float2 B-fragment loads
    for (int i = tid; i < 32 * 200; i += 128) {
        int n = i / 200, p = i % 200;
        int k0 = p >> 3, r = p & 7, tg2 = r >> 1, c = r & 1;
        int k = k0 * 8 + tg2 + 4 * c;
        int grow = (n >> 3) * Hh + u0 + (n & 7);
        Wp[n * 206 + p] = to_tf32(Whh[(size_t)grow * Hh + k]);
    }
    __syncthreads();

    const int m0 = mh * 64 + w * 16;   // global batch base for this warp
    const int lr0 = w * 16;            // local hs row base
    const int g = lane >> 2, tg = lane & 3;
    unsigned* flg = d_flags + (((dir * 2 + mh) * 4 + w) * 32);  // 25 producer flags
    const uint32_t hs_base = (uint32_t)__cvta_generic_to_shared(hs);

    // packed positions (within 8-group) for this lane's two hidden units
    const int pu0 = (((2 * tg) & 3) << 1) | ((2 * tg) >> 2);          // u = u0+2tg
    const int pu1 = (((2 * tg + 1) & 3) << 1) | ((2 * tg + 1) >> 2);  // u = u0+2tg+1

    float cst[4] = {0.f, 0.f, 0.f, 0.f};
    float hreg[4] = {0.f, 0.f, 0.f, 0.f};

    // prefetch gates + mask for step 0
    float2 gx[4][2];
    float mk0, mk1;
    {
        int t0 = dir ? Tt - 1 : 0;
#pragma unroll
        for (int j = 0; j < 4; j++) {
            gx[j][0] = *(const float2*)&d_g[(size_t)((m0 + g) * Tt + t0) * G16 +
                                            dir * 800 + j * 200 + u0 + 2 * tg];
            gx[j][1] = *(const float2*)&d_g[(size_t)((m0 + g + 8) * Tt + t0) * G16 +
                                            dir * 800 + j * 200 + u0 + 2 * tg];
        }
        mk0 = d_mt[t0 * Bsz + m0 + g];
        mk1 = d_mt[t0 * Bsz + m0 + g + 8];
    }

    for (int s = 0; s < Tt; s++) {
        const int t = dir ? (Tt - 1 - s) : s;
        const float* hcur = (s & 1) ? hbuf1 : hbuf0;
        float* hnxt = (s & 1) ? hbuf0 : hbuf1;

        // wait: all 25 producers of this warp-group finished step s-1
        if (s) {
            const unsigned need = (unsigned)s;
            for (;;) {
                unsigned f = (lane < NDB) ? ld_acq(&flg[lane]) : need;
                if (__all_sync(0xffffffffu, f >= need)) break;
            }
        }
        __syncwarp();

        // bulk-stage this warp's 16 batch rows of h_prev (L1-bypassed)
        for (int i = lane; i < 800; i += 32) {
            int r16 = i / 50, c4 = (i % 50) * 4;
            cp16(hs_base + (uint32_t)((lr0 + r16) * 212 + c4) * 4,
                 hcur + (size_t)(m0 + r16) * Hh + c4);
        }
        asm volatile("cp.async.commit_group;");
        asm volatile("cp.async.wait_group 0;");
        __syncwarp();

        float acc[4][4];
#pragma unroll
        for (int j = 0; j < 4; j++)
#pragma unroll
            for (int r = 0; r < 4; r++) acc[j][r] = 0.f;

#pragma unroll
        for (int ik = 0; ik < 25; ik++) {
            const int kb = ik * 8;
            uint32_t a[4];
            {
                float2 f0 = *(const float2*)&hs[(lr0 + g) * 212 + kb + tg * 2];      // packed
                float2 f1 = *(const float2*)&hs[(lr0 + g + 8) * 212 + kb + tg * 2];
                a[0] = __float_as_uint(f0.x);
                a[1] = __float_as_uint(f1.x);
                a[2] = __float_as_uint(f0.y);
                a[3] = __float_as_uint(f1.y);
            }
#pragma unroll
            for (int j = 0; j < 4; j++) {
                float2 bp = *(const float2*)&Wp[(j * 8 + g) * 206 + kb + tg * 2];
                uint32_t bb[2] = { __float_as_uint(bp.x), __float_as_uint(bp.y) };
                mma_tf32(acc[j], a, bb);
            }
        }

#pragma unroll
        for (int j = 0; j < 4; j++) {
            acc[j][0] += gx[j][0].x; acc[j][1] += gx[j][0].y;
            acc[j][2] += gx[j][1].x; acc[j][3] += gx[j][1].y;
        }

        // cell update in registers (MUFU.TANH path)
        float ho[4];
#pragma unroll
        for (int r = 0; r < 4; r++) {
            float m = (r >> 1) ? mk1 : mk0;
            float iv = sig_(acc[0][r]);
            float fv = sig_(acc[1][r]);
            float gv = tanh_(acc[2][r]);
            float ov = sig_(acc[3][r]);
            float cn = fv * cst[r] + iv * gv;
            float hn = ov * tanh_(cn);
            float hnew = m * hn + (1.f - m) * hreg[r];
            cst[r] = m * cn + (1.f - m) * cst[r];
            hreg[r] = hnew;
            ho[r] = m * hn;
        }

        // store h_next (tf32, k-pair-packed positions)
        hnxt[(size_t)(m0 + g) * Hh + u0 + pu0]     = to_tf32(hreg[0]);
        hnxt[(size_t)(m0 + g) * Hh + u0 + pu1]     = to_tf32(hreg[1]);
        hnxt[(size_t)(m0 + g + 8) * Hh + u0 + pu0] = to_tf32(hreg[2]);
        hnxt[(size_t)(m0 + g + 8) * Hh + u0 + pu1] = to_tf32(hreg[3]);

        // release: one st.release per warp (lane0), distinct address per producer
        __syncwarp();
        if (lane == 0) st_rel(&flg[us], (unsigned)(s + 1));

        // ---- tail (off other blocks' critical path) ----
        {
            float2 o0 = make_float2(layer ? ho[0] : to_tf32(ho[0]),
                                    layer ? ho[1] : to_tf32(ho[1]));
            float2 o1 = make_float2(layer ? ho[2] : to_tf32(ho[2]),
                                    layer ? ho[3] : to_tf32(ho[3]));
            // natural layout for both d_x1 (GEMM A input) and d_rnn
            *(float2*)&out[(size_t)((m0 + g) * Tt + t) * IN1 + dir * Hh + u0 + 2 * tg] = o0;
            *(float2*)&out[(size_t)((m0 + g + 8) * Tt + t) * IN1 + dir * Hh + u0 + 2 * tg] = o1;
        }
        if (layer && s == Tt - 1) {
            *(float2*)&d_hfin[dir][(m0 + g) * Hh + u0 + 2 * tg] =
                make_float2(hreg[0], hreg[1]);
            *(float2*)&d_hfin[dir][(m0 + g + 8) * Hh + u0 + 2 * tg] =
                make_float2(hreg[2], hreg[3]);
        }
        if (s < Tt - 1) {
            int tn = dir ? (Tt - 2 - s) : (s + 1);
#pragma unroll
            for (int j = 0; j < 4; j++) {
                gx[j][0] = *(const float2*)&d_g[(size_t)((m0 + g) * Tt + tn) * G16 +
                                                dir * 800 + j * 200 + u0 + 2 * tg];
                gx[j][1] = *(const float2*)&d_g[(size_t)((m0 + g + 8) * Tt + tn) * G16 +
                                                dir * 800 + j * 200 + u0 + 2 * tg];
            }
            mk0 = d_mt[tn * Bsz + m0 + g];
            mk1 = d_mt[tn * Bsz + m0 + g + 8];
        }
    }
}

// ---------------- fused pool: span sums + 3x attention ----------------------
__global__ __launch_bounds__(256)
void pool_kernel(const int* __restrict__ masks, const int* __restrict__ subj,
                 const int* __restrict__ obj) {
    int b = blockIdx.x;
    __shared__ float ssel[Tt];
    __shared__ float osel[Tt];
    __shared__ float qv[3][IN1];     // 0=obj_h 1=subj_h 2=glob_h
    __shared__ float ps[3][Tt];
    __shared__ float red[256];
    int tid = threadIdx.x, lane = tid & 31, w = tid >> 5;

    for (int t = tid; t < Tt; t += 256) {
        int m = masks[b * Tt + t];
        ssel[t] = (subj[b * Tt + t] + m == 0) ? 1.f : 0.f;
        osel[t] = (obj[b * Tt + t] + m == 0) ? 1.f : 0.f;
    }
    __syncthreads();

    for (int f = tid; f < IN1; f += 256) {
        float ss = 0.f, os = 0.f;
        for (int t = 0; t < Tt; t++) {
            float v = d_rnn[(size_t)(b * Tt + t) * IN1 + f];
            ss += v * ssel[t];
            os += v * osel[t];
        }
        qv[0][f] = os;
        qv[1][f] = ss;
        qv[2][f] = (f < Hh) ? d_hfin[1][b * Hh + f] : d_hfin[0][b * Hh + f - Hh];
    }
    __syncthreads();

    for (int t = w; t < Tt; t += 8) {
        const float* row = d_rnn + (size_t)(b * Tt + t) * IN1;
        float s0 = 0.f, s1 = 0.f, s2 = 0.f;
        for (int k = lane; k < IN1; k += 32) {
            float v = row[k];
            s0 += qv[0][k] * v;
            s1 += qv[1][k] * v;
            s2 += qv[2][k] * v;
        }
        for (int o = 16; o; o >>= 1) {
            s0 += __shfl_down_sync(0xffffffffu, s0, o);
            s1 += __shfl_down_sync(0xffffffffu, s1, o);
            s2 += __shfl_down_sync(0xffffffffu, s2, o);
        }
        if (lane == 0) {
            ps[0][t] = s0 * 0.05f;
            ps[1][t] = s1 * 0.05f;
            ps[2][t] = s2 * 0.05f;
        }
    }
    __syncthreads();

    {
        bool pad = masks[b * Tt + tid] != 0;
        if (pad) { ps[0][tid] = -1e9f; ps[1][tid] = -1e9f; ps[2][tid] = -1e9f; }
    }
    __syncthreads();

#pragma unroll
    for (int qi = 0; qi < 3; qi++) {
        float sc = ps[qi][tid];
        red[tid] = sc; __syncthreads();
        for (int o = 128; o; o >>= 1) { if (tid < o) red[tid] = fmaxf(red[tid], red[tid + o]); __syncthreads(); }
        float mx = red[0]; __syncthreads();
        float e = __expf(sc - mx);
        red[tid] = e; __syncthreads();
        for (int o = 128; o; o >>= 1) { if (tid < o) red[tid] += red[tid + o]; __syncthreads(); }
        float inv = 1.f / red[0];
        __syncthreads();
        ps[qi][tid] = e * inv;
        __syncthreads();
    }

    for (int f = tid; f < IN1; f += 256) {
        float a0 = 0.f, a1 = 0.f, a2 = 0.f;
        for (int t = 0; t < Tt; t++) {
            float v = d_rnn[(size_t)(b * Tt + t) * IN1 + f];
            a0 += ps[0][t] * v;
            a1 += ps[1][t] * v;
            a2 += ps[2][t] * v;
        }
        d_att[0][b * IN1 + f] = a0;
        d_att[1][b * IN1 + f] = a1;
        d_att[2][b * IN1 + f] = a2;
    }
}

// ---------------- final MLP head ----------------
__global__ void final_kernel(const float* __restrict__ wo_w, const float* __restrict__ wo_b,
                             const float* __restrict__ ws_w, const float* __restrict__ ws_b,
                             const float* __restrict__ wg_w, const float* __restrict__ wg_b,
                             const float* __restrict__ cls_w, const float* __restrict__ cls_b,
                             float* __restrict__ outp) {
    int b = blockIdx.x;
    __shared__ float hv[Hh];
    int j = threadIdx.x;
    if (j < Hh) {
        float a = wo_b[j] + ws_b[j] + wg_b[j];
        const float* o = &d_att[0][b * IN1];
        const float* s = &d_att[1][b * IN1];
        const float* gq = &d_att[2][b * IN1];
        const float* wo = wo_w + (size_t)j * IN1;
        const float* ws = ws_w + (size_t)j * IN1;
        const float* wg = wg_w + (size_t)j * IN1;
        for (int k = 0; k < IN1; k++)
            a += o[k] * wo[k] + s[k] * ws[k] + gq[k] * wg[k];
        hv[j] = fmaxf(a, 0.f);
    }
    __syncthreads();
    if (j < 64) {
        int n = j >> 5, lane = j & 31;
        float p = 0.f;
        for (int k = lane; k < Hh; k += 32) p += hv[k] * cls_w[n * Hh + k];
        for (int o = 16; o; o >>= 1) p += __shfl_down_sync(0xffffffffu, p, o);
        if (lane == 0) outp[b * NCLASS + n] = p + cls_b[n];
    }
}

// ---------------- launcher ----------------
extern "C" void kernel_launch(void* const* d_in, const int* in_sizes, int n_in,
                              void* d_out, int out_size) {
    const int*   words    = (const int*)d_in[0];
    const int*   masks    = (const int*)d_in[1];
    const int*   pos      = (const int*)d_in[2];
    const int*   ner      = (const int*)d_in[3];
    const int*   subj_pos = (const int*)d_in[4];
    const int*   obj_pos  = (const int*)d_in[5];
    const float* emb_w    = (const float*)d_in[6];
    const float* pos_w    = (const float*)d_in[7];
    const float* ner_w    = (const float*)d_in[8];
    const float* w_ih_l0f = (const float*)d_in[9];
    const float* w_hh_l0f = (const float*)d_in[10];
    const float* b_l0f    = (const float*)d_in[11];
    const float* w_ih_l0b = (const float*)d_in[12];
    const float* w_hh_l0b = (const float*)d_in[13];
    const float* b_l0b    = (const float*)d_in[14];
    const float* w_ih_l1f = (const float*)d_in[15];
    const float* w_hh_l1f = (const float*)d_in[16];
    const float* b_l1f    = (const float*)d_in[17];
    const float* w_ih_l1b = (const float*)d_in[18];
    const float* w_hh_l1b = (const float*)d_in[19];
    const float* b_l1b    = (const float*)d_in[20];
    const float* wo_w     = (const float*)d_in[21];
    const float* wo_b     = (const float*)d_in[22];
    const float* ws_w     = (const float*)d_in[23];
    const float* ws_b     = (const float*)d_in[24];
    const float* wg_w     = (const float*)d_in[25];
    const float* wg_b     = (const float*)d_in[26];
    const float* cls_w    = (const float*)d_in[27];
    const float* cls_b    = (const float*)d_in[28];

    static const int GEMM_SMEM = 3 * GSTG * 4;   // 152064 B
    static const int LSTM_SMEM = 20160 * 4;      // 80640 B
    cudaFuncSetAttribute(gemm_tf32, cudaFuncAttributeMaxDynamicSharedMemorySize, GEMM_SMEM);
    cudaFuncSetAttribute(lstm_layer, cudaFuncAttributeMaxDynamicSharedMemorySize, LSTM_SMEM);

    dim3 ggrid(10, 256);   // N=1600/160, M=32768/128

    embedprep_kernel<<<(BT * 400 + 255) / 256, 256>>>(
        words, pos, ner, emb_w, pos_w, ner_w,
        w_ih_l0f, w_ih_l0b, b_l0f, b_l0b,
        w_ih_l1f, w_ih_l1b, b_l1f, b_l1b, masks);                                        // 0
    gemm_tf32<<<ggrid, 512, GEMM_SMEM>>>(0, 0);                                           // 1
    lstm_layer<<<4 * NDB, 128, LSTM_SMEM>>>(w_hh_l0f, w_hh_l0b, 0);                       // 2
    gemm_tf32<<<ggrid, 512, GEMM_SMEM>>>(1, 1);                                           // 3
    init2_kernel<<<(2 * 2 * Bsz * Hh + 255) / 256, 256>>>();                              // 4
    lstm_layer<<<4 * NDB, 128, LSTM_SMEM>>>(w_hh_l1f, w_hh_l1b, 1);                       // 5
    pool_kernel<<<Bsz, 256>>>(masks, subj_pos, obj_pos);                                  // 6
    final_kernel<<<Bsz, 256>>>(wo_w, wo_b, ws_w, ws_b, wg_w, wg_b, cls_w, cls_b,
                               (float*)d_out);                                            // 7
}

// round 12
// speedup vs baseline: 1.1919x; 1.1919x over previous
#include <cuda_runtime.h>
#include <cstdint>

#define Bsz 128
#define Tt 256
#define Hh 200
#define IN1 400
#define BT (Bsz*Tt)
#define NCLASS 2
#define G16 1600

// ---------------- device scratch (static, no allocation) ----------------
__device__ __align__(16) float d_x0[BT*400];        // embeddings, tf32, natural layout
__device__ __align__(16) float d_x1[BT*400];        // layer0 output (tf32, natural)
__device__ __align__(16) float d_rnn[BT*400];       // layer1 output (fp32, natural)
__device__ __align__(16) float d_g[(size_t)BT*G16]; // gates: [bt][fwd 800 | bwd 800]
__device__ __align__(16) float d_h[2][2][Bsz*Hh];   // [dir][buf][b*200+u] k-pair-packed
__device__ __align__(16) float d_hfin[2][Bsz*Hh];   // natural
__device__ __align__(16) float d_att[3][Bsz*IN1];
__device__ __align__(16) float d_wcat[2][G16*400];  // padded tf32 W_ih, k pair-packed
__device__ __align__(16) float d_bcat[2][G16];
__device__ __align__(16) float d_mt[Tt*Bsz];        // keep-mask transposed [t][b]
__device__ unsigned d_barc3[512];                   // 16 groups x 32 per-lane counters

// ---------------- helpers ----------------
__device__ __forceinline__ float tanh_(float x) {
    float r;
    asm("tanh.approx.f32 %0, %1;" : "=f"(r) : "f"(x));
    return r;
}
__device__ __forceinline__ float sig_(float x) {
    return fmaf(tanh_(0.5f * x), 0.5f, 0.5f);
}
__device__ __forceinline__ float to_tf32(float x) {
    float r;
    asm("cvt.rna.tf32.f32 %0, %1;" : "=f"(r) : "f"(x));
    return r;
}
__device__ __forceinline__ void mma_tf32(float* d, const uint32_t* a, const uint32_t* b) {
    asm volatile(
        "mma.sync.aligned.m16n8k8.row.col.f32.tf32.tf32.f32 "
        "{%0,%1,%2,%3}, {%4,%5,%6,%7}, {%8,%9}, {%0,%1,%2,%3};"
        : "+f"(d[0]), "+f"(d[1]), "+f"(d[2]), "+f"(d[3])
        : "r"(a[0]), "r"(a[1]), "r"(a[2]), "r"(a[3]), "r"(b[0]), "r"(b[1]));
}
__device__ __forceinline__ void cp16(uint32_t saddr, const void* gaddr) {
    asm volatile("cp.async.cg.shared.global [%0], [%1], 16;" :: "r"(saddr), "l"(gaddr));
}
__device__ __forceinline__ unsigned ld_acq(const unsigned* p) {
    unsigned v;
    asm volatile("ld.acquire.gpu.global.u32 %0, [%1];" : "=r"(v) : "l"(p) : "memory");
    return v;
}
__device__ __forceinline__ void red_rel(unsigned* p) {
    asm volatile("red.release.gpu.global.add.u32 [%0], %1;" :: "l"(p), "r"(1u) : "memory");
}

// ---------------- fused embed + prep ----------------------------------------
// d_x0 natural layout; wcat k-pair-packed: packed position p holds source
// k = k0*8 + tg + 4c where p = k0*8 + tg*2 + c.
__global__ void embedprep_kernel(const int* __restrict__ words, const int* __restrict__ pos,
                                 const int* __restrict__ ner,
                                 const float* __restrict__ emb_w, const float* __restrict__ pos_w,
                                 const float* __restrict__ ner_w,
                                 const float* __restrict__ wf0, const float* __restrict__ wb0,
                                 const float* __restrict__ bf0, const float* __restrict__ bb0,
                                 const float* __restrict__ wf1, const float* __restrict__ wb1,
                                 const float* __restrict__ bf1, const float* __restrict__ bb1,
                                 const int* __restrict__ masks) {
    int i = blockIdx.x * blockDim.x + threadIdx.x;
    if (i < BT * 400) {
        int c = i % 400, bt = i / 400;
        float v = 0.f;
        if (c < 300)        v = emb_w[(size_t)words[bt] * 300 + c];
        else if (c < 330)   v = pos_w[(size_t)pos[bt] * 30 + (c - 300)];
        else if (c < 360)   v = ner_w[(size_t)ner[bt] * 30 + (c - 330)];
        d_x0[i] = to_tf32(v);
    }
    if (i < G16 * 400) {
        int n = i / 400, p = i % 400;
        int k0 = p >> 3, r = p & 7, tg = r >> 1, c = r & 1;
        int k = k0 * 8 + tg + 4 * c;
        int nn = (n < 800) ? n : n - 800;
        float v0 = 0.f, v1 = 0.f;
        if (k < 360) {
            const float* W = (n < 800) ? wf0 : wb0;
            v0 = to_tf32(W[(size_t)nn * 360 + k]);
        }
        {
            const float* W = (n < 800) ? wf1 : wb1;
            v1 = to_tf32(W[(size_t)nn * 400 + k]);
        }
        d_wcat[0][i] = v0;
        d_wcat[1][i] = v1;
    }
    if (i < G16) {
        d_bcat[0][i] = (i < 800) ? bf0[i] : bb0[i - 800];
        d_bcat[1][i] = (i < 800) ? bf1[i] : bb1[i - 800];
    }
    if (i < Tt * Bsz) {
        int t = i / Bsz, b = i % Bsz;
        d_mt[i] = (masks[b * Tt + t] == 0) ? 1.f : 0.f;
    }
    if (i < 2 * 2 * Bsz * Hh) ((float*)d_h)[i] = 0.f;
    if (i < 512) d_barc3[i] = 0;
}

// ---------------- init between layers: reset h + counters ----------------
__global__ void init2_kernel() {
    int i = blockIdx.x * blockDim.x + threadIdx.x;
    if (i < 2 * 2 * Bsz * Hh) ((float*)d_h)[i] = 0.f;
    if (i < 512) d_barc3[i] = 0;
}

// ---------------- TF32 GEMM: d_g[32768,1600] = A[32768,400] @ Wcat^T + bias -
// BM=128, BN=160, BK=40, 3-stage cp.async ring. A natural (scalar LDS),
// B k-pair-packed (LDS.64). R9/R11-proven mainloop (385us).
#define GSTG 12672   // floats per stage: A 128*44 + B 160*44

__global__ __launch_bounds__(512, 1)
void gemm_tf32(int asel, int layer) {
    extern __shared__ float smg[];
    const float* A = asel ? d_x1 : d_x0;
    const float* Wc = d_wcat[layer];
    const float* bc = d_bcat[layer];

    const int tid = threadIdx.x;
    const int lane = tid & 31, w = tid >> 5;
    const int wm = w & 3, wn = w >> 2;
    const int g = lane >> 2, tg = lane & 3;
    const int m0 = blockIdx.y * 128, n0 = blockIdx.x * 160;

    const uint32_t sbase = (uint32_t)__cvta_generic_to_shared(smg);

    float acc[2][5][4];
#pragma unroll
    for (int i = 0; i < 2; i++)
#pragma unroll
        for (int j = 0; j < 5; j++)
#pragma unroll
            for (int r = 0; r < 4; r++) acc[i][j][r] = 0.f;

#define STAGE(IT, S) do {                                                      \
        int k0 = (IT) * 40;                                                    \
        uint32_t aB = sbase + (uint32_t)((S) * GSTG) * 4;                      \
        uint32_t bB = aB + 5632u * 4u;                                         \
        for (int i = tid; i < 1280; i += 512) {                                \
            int row = i / 10, c4 = (i % 10) * 4;                               \
            cp16(aB + (uint32_t)(row * 44 + c4) * 4,                           \
                 A + (size_t)(m0 + row) * 400 + k0 + c4);                      \
        }                                                                      \
        for (int i = tid; i < 1600; i += 512) {                                \
            int row = i / 10, c4 = (i % 10) * 4;                               \
            cp16(bB + (uint32_t)(row * 44 + c4) * 4,                           \
                 Wc + (size_t)(n0 + row) * 400 + k0 + c4);                     \
        }                                                                      \
        asm volatile("cp.async.commit_group;");                                \
    } while (0)

    STAGE(0, 0);
    STAGE(1, 1);

    for (int it = 0; it < 10; it++) {
        asm volatile("cp.async.wait_group 1;");
        __syncthreads();
        if (it + 2 < 10) STAGE(it + 2, (it + 2) % 3);

        const float* As = smg + (it % 3) * GSTG;
        const float* Bs = As + 5632;
#pragma unroll
        for (int ks = 0; ks < 5; ks++) {
            const int kb = ks * 8;
            uint32_t afr[2][4];
#pragma unroll
            for (int mi = 0; mi < 2; mi++) {
                int m = wm * 32 + mi * 16 + g;
                afr[mi][0] = __float_as_uint(As[m * 44 + kb + tg]);
                afr[mi][1] = __float_as_uint(As[(m + 8) * 44 + kb + tg]);
                afr[mi][2] = __float_as_uint(As[m * 44 + kb + tg + 4]);
                afr[mi][3] = __float_as_uint(As[(m + 8) * 44 + kb + tg + 4]);
            }
            uint32_t bfr[5][2];
#pragma unroll
            for (int nj = 0; nj < 5; nj++) {
                int n = wn * 40 + nj * 8 + g;
                float2 bp = *(const float2*)&Bs[n * 44 + kb + tg * 2];  // pair-packed
                bfr[nj][0] = __float_as_uint(bp.x);
                bfr[nj][1] = __float_as_uint(bp.y);
            }
#pragma unroll
            for (int mi = 0; mi < 2; mi++)
#pragma unroll
                for (int nj = 0; nj < 5; nj++)
                    mma_tf32(acc[mi][nj], afr[mi], bfr[nj]);
        }
    }
#undef STAGE

#pragma unroll
    for (int mi = 0; mi < 2; mi++) {
        int mrow = m0 + wm * 32 + mi * 16 + g;
#pragma unroll
        for (int nj = 0; nj < 5; nj++) {
            int ncol = n0 + wn * 40 + nj * 8 + 2 * tg;
            float bx = bc[ncol], by = bc[ncol + 1];
            *(float2*)(d_g + (size_t)mrow * G16 + ncol) =
                make_float2(acc[mi][nj][0] + bx, acc[mi][nj][1] + by);
            *(float2*)(d_g + (size_t)(mrow + 8) * G16 + ncol) =
                make_float2(acc[mi][nj][2] + bx, acc[mi][nj][3] + by);
        }
    }
}

// ---------------- persistent tensor-core bidirectional LSTM (R10 proven) ---
// 100 blocks = 2 dir x 2 batch-halves x 25 u-slices. 128 thr (4 warps).
// Sync: per-lane REDG counters (proven best across R5/R6/R8/R11 experiments).
// d_h k-pair-packed -> A-fragment loads are LDS.64. MUFU activations.
#define NDB 25

__global__ __launch_bounds__(128, 1)
void lstm_layer(const float* __restrict__ Whhf, const float* __restrict__ Whhb, int layer) {
    extern __shared__ float sm[];
    float* hs = sm;            // [64][212] = 13568 floats
    float* Wp = sm + 13568;    // [32][206] = 6592 floats

    const int tid = threadIdx.x;
    const int lane = tid & 31, w = tid >> 5;   // w in 0..3
    const int bx = blockIdx.x;
    const int dir = bx / (2 * NDB);
    const int mh  = (bx / NDB) & 1;
    const int us  = bx % NDB;
    const int u0  = us * 8;
    const float* Whh = dir ? Whhb : Whhf;
    float* out = layer ? d_rnn : d_x1;
    float* hbuf0 = d_h[dir][0];
    float* hbuf1 = d_h[dir][1];

    // pack W_hh slice, tf32, pair-packed for float2 B-fragment loads
    for (int i = tid; i < 32 * 200; i += 128) {
        int n = i / 200, p = i % 200;
        int k0 = p >> 3, r = p & 7, tg2 = r >> 1, c = r & 1;
        int k = k0 * 8 + tg2 + 4 * c;
        int grow = (n >> 3) * Hh + u0 + (n & 7);
        Wp[n * 206 + p] = to_tf32(Whh[(size_t)grow * Hh + k]);
    }
    __syncthreads();

    const int m0 = mh * 64 + w * 16;   // global batch base for this warp
    const int lr0 = w * 16;            // local hs row base
    const int g = lane >> 2, tg = lane & 3;
    unsigned* bar = d_barc3 + (((dir * 2 + mh) * 4 + w) * 32);
    const uint32_t hs_base = (uint32_t)__cvta_generic_to_shared(hs);

    // packed positions (within 8-group) for this lane's two hidden units
    const int pu0 = (((2 * tg) & 3) << 1) | ((2 * tg) >> 2);          // u = u0+2tg
    const int pu1 = (((2 * tg + 1) & 3) << 1) | ((2 * tg + 1) >> 2);  // u = u0+2tg+1

    float cst[4] = {0.f, 0.f, 0.f, 0.f};
    float hreg[4] = {0.f, 0.f, 0.f, 0.f};

    // prefetch gates + mask for step 0
    float2 gx[4][2];
    float mk0, mk1;
    {
        int t0 = dir ? Tt - 1 : 0;
#pragma unroll
        for (int j = 0; j < 4; j++) {
            gx[j][0] = *(const float2*)&d_g[(size_t)((m0 + g) * Tt + t0) * G16 +
                                            dir * 800 + j * 200 + u0 + 2 * tg];
            gx[j][1] = *(const float2*)&d_g[(size_t)((m0 + g + 8) * Tt + t0) * G16 +
                                            dir * 800 + j * 200 + u0 + 2 * tg];
        }
        mk0 = d_mt[t0 * Bsz + m0 + g];
        mk1 = d_mt[t0 * Bsz + m0 + g + 8];
    }

    for (int s = 0; s < Tt; s++) {
        const int t = dir ? (Tt - 1 - s) : s;
        const float* hcur = (s & 1) ? hbuf1 : hbuf0;
        float* hnxt = (s & 1) ? hbuf0 : hbuf1;

        // wait for all 25 blocks of this warp-group to finish step s-1
        if (s) {
            unsigned tgt = (unsigned)NDB * (unsigned)s;
            while (ld_acq(&bar[lane]) < tgt) {}
        }
        __syncwarp();

        // bulk-stage this warp's 16 batch rows of h_prev (L1-bypassed)
        for (int i = lane; i < 800; i += 32) {
            int r16 = i / 50, c4 = (i % 50) * 4;
            cp16(hs_base + (uint32_t)((lr0 + r16) * 212 + c4) * 4,
                 hcur + (size_t)(m0 + r16) * Hh + c4);
        }
        asm volatile("cp.async.commit_group;");
        asm volatile("cp.async.wait_group 0;");
        __syncwarp();

        float acc[4][4];
#pragma unroll
        for (int j = 0; j < 4; j++)
#pragma unroll
            for (int r = 0; r < 4; r++) acc[j][r] = 0.f;

#pragma unroll
        for (int ik = 0; ik < 25; ik++) {
            const int kb = ik * 8;
            uint32_t a[4];
            {
                float2 f0 = *(const float2*)&hs[(lr0 + g) * 212 + kb + tg * 2];      // packed
                float2 f1 = *(const float2*)&hs[(lr0 + g + 8) * 212 + kb + tg * 2];
                a[0] = __float_as_uint(f0.x);
                a[1] = __float_as_uint(f1.x);
                a[2] = __float_as_uint(f0.y);
                a[3] = __float_as_uint(f1.y);
            }
#pragma unroll
            for (int j = 0; j < 4; j++) {
                float2 bp = *(const float2*)&Wp[(j * 8 + g) * 206 + kb + tg * 2];
                uint32_t bb[2] = { __float_as_uint(bp.x), __float_as_uint(bp.y) };
                mma_tf32(acc[j], a, bb);
            }
        }

#pragma unroll
        for (int j = 0; j < 4; j++) {
            acc[j][0] += gx[j][0].x; acc[j][1] += gx[j][0].y;
            acc[j][2] += gx[j][1].x; acc[j][3] += gx[j][1].y;
        }

        // cell update in registers (MUFU.TANH path)
        float ho[4];
#pragma unroll
        for (int r = 0; r < 4; r++) {
            float m = (r >> 1) ? mk1 : mk0;
            float iv = sig_(acc[0][r]);
            float fv = sig_(acc[1][r]);
            float gv = tanh_(acc[2][r]);
            float ov = sig_(acc[3][r]);
            float cn = fv * cst[r] + iv * gv;
            float hn = ov * tanh_(cn);
            float hnew = m * hn + (1.f - m) * hreg[r];
            cst[r] = m * cn + (1.f - m) * cst[r];
            hreg[r] = hnew;
            ho[r] = m * hn;
        }

        // store h_next (tf32, k-pair-packed positions)
        hnxt[(size_t)(m0 + g) * Hh + u0 + pu0]     = to_tf32(hreg[0]);
        hnxt[(size_t)(m0 + g) * Hh + u0 + pu1]     = to_tf32(hreg[1]);
        hnxt[(size_t)(m0 + g + 8) * Hh + u0 + pu0] = to_tf32(hreg[2]);
        hnxt[(size_t)(m0 + g + 8) * Hh + u0 + pu1] = to_tf32(hreg[3]);

        // release: each lane orders its own stores (spread-address REDG)
        red_rel(&bar[lane]);

        // ---- tail (off other blocks' critical path) ----
        {
            float2 o0 = make_float2(layer ? ho[0] : to_tf32(ho[0]),
                                    layer ? ho[1] : to_tf32(ho[1]));
            float2 o1 = make_float2(layer ? ho[2] : to_tf32(ho[2]),
                                    layer ? ho[3] : to_tf32(ho[3]));
            // natural layout for both d_x1 (GEMM A input) and d_rnn
            *(float2*)&out[(size_t)((m0 + g) * Tt + t) * IN1 + dir * Hh + u0 + 2 * tg] = o0;
            *(float2*)&out[(size_t)((m0 + g + 8) * Tt + t) * IN1 + dir * Hh + u0 + 2 * tg] = o1;
        }
        if (layer && s == Tt - 1) {
            *(float2*)&d_hfin[dir][(m0 + g) * Hh + u0 + 2 * tg] =
                make_float2(hreg[0], hreg[1]);
            *(float2*)&d_hfin[dir][(m0 + g + 8) * Hh + u0 + 2 * tg] =
                make_float2(hreg[2], hreg[3]);
        }
        if (s < Tt - 1) {
            int tn = dir ? (Tt - 2 - s) : (s + 1);
#pragma unroll
            for (int j = 0; j < 4; j++) {
                gx[j][0] = *(const float2*)&d_g[(size_t)((m0 + g) * Tt + tn) * G16 +
                                                dir * 800 + j * 200 + u0 + 2 * tg];
                gx[j][1] = *(const float2*)&d_g[(size_t)((m0 + g + 8) * Tt + tn) * G16 +
                                                dir * 800 + j * 200 + u0 + 2 * tg];
            }
            mk0 = d_mt[tn * Bsz + m0 + g];
            mk1 = d_mt[tn * Bsz + m0 + g + 8];
        }
    }
}

// ---------------- fused pool: span sums + 3x attention ----------------------
__global__ __launch_bounds__(256)
void pool_kernel(const int* __restrict__ masks, const int* __restrict__ subj,
                 const int* __restrict__ obj) {
    int b = blockIdx.x;
    __shared__ float ssel[Tt];
    __shared__ float osel[Tt];
    __shared__ float qv[3][IN1];     // 0=obj_h 1=subj_h 2=glob_h
    __shared__ float ps[3][Tt];
    __shared__ float red[256];
    int tid = threadIdx.x, lane = tid & 31, w = tid >> 5;

    for (int t = tid; t < Tt; t += 256) {
        int m = masks[b * Tt + t];
        ssel[t] = (subj[b * Tt + t] + m == 0) ? 1.f : 0.f;
        osel[t] = (obj[b * Tt + t] + m == 0) ? 1.f : 0.f;
    }
    __syncthreads();

    for (int f = tid; f < IN1; f += 256) {
        float ss = 0.f, os = 0.f;
        for (int t = 0; t < Tt; t++) {
            float v = d_rnn[(size_t)(b * Tt + t) * IN1 + f];
            ss += v * ssel[t];
            os += v * osel[t];
        }
        qv[0][f] = os;
        qv[1][f] = ss;
        qv[2][f] = (f < Hh) ? d_hfin[1][b * Hh + f] : d_hfin[0][b * Hh + f - Hh];
    }
    __syncthreads();

    for (int t = w; t < Tt; t += 8) {
        const float* row = d_rnn + (size_t)(b * Tt + t) * IN1;
        float s0 = 0.f, s1 = 0.f, s2 = 0.f;
        for (int k = lane; k < IN1; k += 32) {
            float v = row[k];
            s0 += qv[0][k] * v;
            s1 += qv[1][k] * v;
            s2 += qv[2][k] * v;
        }
        for (int o = 16; o; o >>= 1) {
            s0 += __shfl_down_sync(0xffffffffu, s0, o);
            s1 += __shfl_down_sync(0xffffffffu, s1, o);
            s2 += __shfl_down_sync(0xffffffffu, s2, o);
        }
        if (lane == 0) {
            ps[0][t] = s0 * 0.05f;
            ps[1][t] = s1 * 0.05f;
            ps[2][t] = s2 * 0.05f;
        }
    }
    __syncthreads();

    {
        bool pad = masks[b * Tt + tid] != 0;
        if (pad) { ps[0][tid] = -1e9f; ps[1][tid] = -1e9f; ps[2][tid] = -1e9f; }
    }
    __syncthreads();

#pragma unroll
    for (int qi = 0; qi < 3; qi++) {
        float sc = ps[qi][tid];
        red[tid] = sc; __syncthreads();
        for (int o = 128; o; o >>= 1) { if (tid < o) red[tid] = fmaxf(red[tid], red[tid + o]); __syncthreads(); }
        float mx = red[0]; __syncthreads();
        float e = __expf(sc - mx);
        red[tid] = e; __syncthreads();
        for (int o = 128; o; o >>= 1) { if (tid < o) red[tid] += red[tid + o]; __syncthreads(); }
        float inv = 1.f / red[0];
        __syncthreads();
        ps[qi][tid] = e * inv;
        __syncthreads();
    }

    for (int f = tid; f < IN1; f += 256) {
        float a0 = 0.f, a1 = 0.f, a2 = 0.f;
        for (int t = 0; t < Tt; t++) {
            float v = d_rnn[(size_t)(b * Tt + t) * IN1 + f];
            a0 += ps[0][t] * v;
            a1 += ps[1][t] * v;
            a2 += ps[2][t] * v;
        }
        d_att[0][b * IN1 + f] = a0;
        d_att[1][b * IN1 + f] = a1;
        d_att[2][b * IN1 + f] = a2;
    }
}

// ---------------- final MLP head ----------------
__global__ void final_kernel(const float* __restrict__ wo_w, const float* __restrict__ wo_b,
                             const float* __restrict__ ws_w, const float* __restrict__ ws_b,
                             const float* __restrict__ wg_w, const float* __restrict__ wg_b,
                             const float* __restrict__ cls_w, const float* __restrict__ cls_b,
                             float* __restrict__ outp) {
    int b = blockIdx.x;
    __shared__ float hv[Hh];
    int j = threadIdx.x;
    if (j < Hh) {
        float a = wo_b[j] + ws_b[j] + wg_b[j];
        const float* o = &d_att[0][b * IN1];
        const float* s = &d_att[1][b * IN1];
        const float* gq = &d_att[2][b * IN1];
        const float* wo = wo_w + (size_t)j * IN1;
        const float* ws = ws_w + (size_t)j * IN1;
        const float* wg = wg_w + (size_t)j * IN1;
        for (int k = 0; k < IN1; k++)
            a += o[k] * wo[k] + s[k] * ws[k] + gq[k] * wg[k];
        hv[j] = fmaxf(a, 0.f);
    }
    __syncthreads();
    if (j < 64) {
        int n = j >> 5, lane = j & 31;
        float p = 0.f;
        for (int k = lane; k < Hh; k += 32) p += hv[k] * cls_w[n * Hh + k];
        for (int o = 16; o; o >>= 1) p += __shfl_down_sync(0xffffffffu, p, o);
        if (lane == 0) outp[b * NCLASS + n] = p + cls_b[n];
    }
}

// ---------------- launcher ----------------
extern "C" void kernel_launch(void* const* d_in, const int* in_sizes, int n_in,
                              void* d_out, int out_size) {
    const int*   words    = (const int*)d_in[0];
    const int*   masks    = (const int*)d_in[1];
    const int*   pos      = (const int*)d_in[2];
    const int*   ner      = (const int*)d_in[3];
    const int*   subj_pos = (const int*)d_in[4];
    const int*   obj_pos  = (const int*)d_in[5];
    const float* emb_w    = (const float*)d_in[6];
    const float* pos_w    = (const float*)d_in[7];
    const float* ner_w    = (const float*)d_in[8];
    const float* w_ih_l0f = (const float*)d_in[9];
    const float* w_hh_l0f = (const float*)d_in[10];
    const float* b_l0f    = (const float*)d_in[11];
    const float* w_ih_l0b = (const float*)d_in[12];
    const float* w_hh_l0b = (const float*)d_in[13];
    const float* b_l0b    = (const float*)d_in[14];
    const float* w_ih_l1f = (const float*)d_in[15];
    const float* w_hh_l1f = (const float*)d_in[16];
    const float* b_l1f    = (const float*)d_in[17];
    const float* w_ih_l1b = (const float*)d_in[18];
    const float* w_hh_l1b = (const float*)d_in[19];
    const float* b_l1b    = (const float*)d_in[20];
    const float* wo_w     = (const float*)d_in[21];
    const float* wo_b     = (const float*)d_in[22];
    const float* ws_w     = (const float*)d_in[23];
    const float* ws_b     = (const float*)d_in[24];
    const float* wg_w     = (const float*)d_in[25];
    const float* wg_b     = (const float*)d_in[26];
    const float* cls_w    = (const float*)d_in[27];
    const float* cls_b    = (const float*)d_in[28];

    static const int GEMM_SMEM = 3 * GSTG * 4;   // 152064 B
    static const int LSTM_SMEM = 20160 * 4;      // 80640 B
    cudaFuncSetAttribute(gemm_tf32, cudaFuncAttributeMaxDynamicSharedMemorySize, GEMM_SMEM);
    cudaFuncSetAttribute(lstm_layer, cudaFuncAttributeMaxDynamicSharedMemorySize, LSTM_SMEM);

    dim3 ggrid(10, 256);   // N=1600/160, M=32768/128

    embedprep_kernel<<<(BT * 400 + 255) / 256, 256>>>(
        words, pos, ner, emb_w, pos_w, ner_w,
        w_ih_l0f, w_ih_l0b, b_l0f, b_l0b,
        w_ih_l1f, w_ih_l1b, b_l1f, b_l1b, masks);                                        // 0
    gemm_tf32<<<ggrid, 512, GEMM_SMEM>>>(0, 0);                                           // 1
    lstm_layer<<<4 * NDB, 128, LSTM_SMEM>>>(w_hh_l0f, w_hh_l0b, 0);                       // 2
    gemm_tf32<<<ggrid, 512, GEMM_SMEM>>>(1, 1);                                           // 3
    init2_kernel<<<(2 * 2 * Bsz * Hh + 255) / 256, 256>>>();                              // 4
    lstm_layer<<<4 * NDB, 128, LSTM_SMEM>>>(w_hh_l1f, w_hh_l1b, 1);                       // 5
    pool_kernel<<<Bsz, 256>>>(masks, subj_pos, obj_pos);                                  // 6
    final_kernel<<<Bsz, 256>>>(wo_w, wo_b, ws_w, ws_b, wg_w, wg_b, cls_w, cls_b,
                               (float*)d_out);                                            // 7
}

// round 13
// speedup vs baseline: 1.2297x; 1.0317x over previous
#include <cuda_runtime.h>
#include <cstdint>

#define Bsz 128
#define Tt 256
#define Hh 200
#define IN1 400
#define BT (Bsz*Tt)
#define NCLASS 2
#define G16 1600

// ---------------- device scratch (static, no allocation) ----------------
__device__ __align__(16) float d_x0[BT*400];        // embeddings, tf32, natural layout
__device__ __align__(16) float d_x1[BT*400];        // layer0 output (tf32, natural)
__device__ __align__(16) float d_rnn[BT*400];       // layer1 output (fp32, natural)
__device__ __align__(16) float d_g[(size_t)BT*G16]; // gates: [bt][fwd 800 | bwd 800]
__device__ __align__(16) float d_h[2][2][2][Bsz*Hh];// [layer][dir][buf][b*200+u] packed
__device__ __align__(16) float d_hfin[2][Bsz*Hh];   // natural
__device__ __align__(16) float d_att[3][Bsz*IN1];
__device__ __align__(16) float d_wcat[2][G16*400];  // padded tf32 W_ih, k pair-packed
__device__ __align__(16) float d_bcat[2][G16];
__device__ __align__(16) float d_mt[Tt*Bsz];        // keep-mask transposed [t][b]
__device__ unsigned d_barc[2][512];                 // per-layer: 16 groups x 32 counters

// ---------------- helpers ----------------
__device__ __forceinline__ float tanh_(float x) {
    float r;
    asm("tanh.approx.f32 %0, %1;" : "=f"(r) : "f"(x));
    return r;
}
__device__ __forceinline__ float sig_(float x) {
    return fmaf(tanh_(0.5f * x), 0.5f, 0.5f);
}
__device__ __forceinline__ float to_tf32(float x) {
    float r;
    asm("cvt.rna.tf32.f32 %0, %1;" : "=f"(r) : "f"(x));
    return r;
}
__device__ __forceinline__ void mma_tf32(float* d, const uint32_t* a, const uint32_t* b) {
    asm volatile(
        "mma.sync.aligned.m16n8k8.row.col.f32.tf32.tf32.f32 "
        "{%0,%1,%2,%3}, {%4,%5,%6,%7}, {%8,%9}, {%0,%1,%2,%3};"
        : "+f"(d[0]), "+f"(d[1]), "+f"(d[2]), "+f"(d[3])
        : "r"(a[0]), "r"(a[1]), "r"(a[2]), "r"(a[3]), "r"(b[0]), "r"(b[1]));
}
__device__ __forceinline__ void cp16(uint32_t saddr, const void* gaddr) {
    asm volatile("cp.async.cg.shared.global [%0], [%1], 16;" :: "r"(saddr), "l"(gaddr));
}
__device__ __forceinline__ unsigned ld_acq(const unsigned* p) {
    unsigned v;
    asm volatile("ld.acquire.gpu.global.u32 %0, [%1];" : "=r"(v) : "l"(p) : "memory");
    return v;
}
__device__ __forceinline__ void red_rel(unsigned* p) {
    asm volatile("red.release.gpu.global.add.u32 [%0], %1;" :: "l"(p), "r"(1u) : "memory");
}

// ---------------- fused embed + prep (also zeroes both layers' h + counters)
__global__ void embedprep_kernel(const int* __restrict__ words, const int* __restrict__ pos,
                                 const int* __restrict__ ner,
                                 const float* __restrict__ emb_w, const float* __restrict__ pos_w,
                                 const float* __restrict__ ner_w,
                                 const float* __restrict__ wf0, const float* __restrict__ wb0,
                                 const float* __restrict__ bf0, const float* __restrict__ bb0,
                                 const float* __restrict__ wf1, const float* __restrict__ wb1,
                                 const float* __restrict__ bf1, const float* __restrict__ bb1,
                                 const int* __restrict__ masks) {
    int i = blockIdx.x * blockDim.x + threadIdx.x;
    if (i < BT * 400) {
        int c = i % 400, bt = i / 400;
        float v = 0.f;
        if (c < 300)        v = emb_w[(size_t)words[bt] * 300 + c];
        else if (c < 330)   v = pos_w[(size_t)pos[bt] * 30 + (c - 300)];
        else if (c < 360)   v = ner_w[(size_t)ner[bt] * 30 + (c - 330)];
        d_x0[i] = to_tf32(v);
    }
    if (i < G16 * 400) {
        int n = i / 400, p = i % 400;
        int k0 = p >> 3, r = p & 7, tg = r >> 1, c = r & 1;
        int k = k0 * 8 + tg + 4 * c;
        int nn = (n < 800) ? n : n - 800;
        float v0 = 0.f, v1 = 0.f;
        if (k < 360) {
            const float* W = (n < 800) ? wf0 : wb0;
            v0 = to_tf32(W[(size_t)nn * 360 + k]);
        }
        {
            const float* W = (n < 800) ? wf1 : wb1;
            v1 = to_tf32(W[(size_t)nn * 400 + k]);
        }
        d_wcat[0][i] = v0;
        d_wcat[1][i] = v1;
    }
    if (i < G16) {
        d_bcat[0][i] = (i < 800) ? bf0[i] : bb0[i - 800];
        d_bcat[1][i] = (i < 800) ? bf1[i] : bb1[i - 800];
    }
    if (i < Tt * Bsz) {
        int t = i / Bsz, b = i % Bsz;
        d_mt[i] = (masks[b * Tt + t] == 0) ? 1.f : 0.f;
    }
    if (i < 2 * 2 * 2 * Bsz * Hh) ((float*)d_h)[i] = 0.f;
    if (i < 2 * 512) ((unsigned*)d_barc)[i] = 0;
}

// ---------------- TF32 GEMM: d_g[32768,1600] = A[32768,400] @ Wcat^T + bias -
// 256 threads, 8 warps (2x4), warp tile 64x40 (R2-proven high-ILP shape),
// BK=40, 3-stage cp.async ring, B k-pair-packed (LDS.64 fragments).
#define GSTG 12672   // floats per stage: A 128*44 + B 160*44

__global__ __launch_bounds__(256, 1)
void gemm_tf32(int asel, int layer) {
    extern __shared__ float smg[];
    const float* A = asel ? d_x1 : d_x0;
    const float* Wc = d_wcat[layer];
    const float* bc = d_bcat[layer];

    const int tid = threadIdx.x;
    const int lane = tid & 31, w = tid >> 5;
    const int wm = w & 1, wn = w >> 1;          // 2 x 4 warp grid
    const int g = lane >> 2, tg = lane & 3;
    const int m0 = blockIdx.y * 128, n0 = blockIdx.x * 160;

    const uint32_t sbase = (uint32_t)__cvta_generic_to_shared(smg);

    float acc[4][5][4];
#pragma unroll
    for (int i = 0; i < 4; i++)
#pragma unroll
        for (int j = 0; j < 5; j++)
#pragma unroll
            for (int r = 0; r < 4; r++) acc[i][j][r] = 0.f;

#define STAGE(IT, S) do {                                                      \
        int k0 = (IT) * 40;                                                    \
        uint32_t aB = sbase + (uint32_t)((S) * GSTG) * 4;                      \
        uint32_t bB = aB + 5632u * 4u;                                         \
        for (int i = tid; i < 1280; i += 256) {                                \
            int row = i / 10, c4 = (i % 10) * 4;                               \
            cp16(aB + (uint32_t)(row * 44 + c4) * 4,                           \
                 A + (size_t)(m0 + row) * 400 + k0 + c4);                      \
        }                                                                      \
        for (int i = tid; i < 1600; i += 256) {                                \
            int row = i / 10, c4 = (i % 10) * 4;                               \
            cp16(bB + (uint32_t)(row * 44 + c4) * 4,                           \
                 Wc + (size_t)(n0 + row) * 400 + k0 + c4);                     \
        }                                                                      \
        asm volatile("cp.async.commit_group;");                                \
    } while (0)

    STAGE(0, 0);
    STAGE(1, 1);

    for (int it = 0; it < 10; it++) {
        asm volatile("cp.async.wait_group 1;");
        __syncthreads();
        if (it + 2 < 10) STAGE(it + 2, (it + 2) % 3);

        const float* As = smg + (it % 3) * GSTG;
        const float* Bs = As + 5632;
#pragma unroll
        for (int ks = 0; ks < 5; ks++) {
            const int kb = ks * 8;
            uint32_t afr[4][4];
#pragma unroll
            for (int mi = 0; mi < 4; mi++) {
                int m = wm * 64 + mi * 16 + g;
                afr[mi][0] = __float_as_uint(As[m * 44 + kb + tg]);
                afr[mi][1] = __float_as_uint(As[(m + 8) * 44 + kb + tg]);
                afr[mi][2] = __float_as_uint(As[m * 44 + kb + tg + 4]);
                afr[mi][3] = __float_as_uint(As[(m + 8) * 44 + kb + tg + 4]);
            }
            uint32_t bfr[5][2];
#pragma unroll
            for (int nj = 0; nj < 5; nj++) {
                int n = wn * 40 + nj * 8 + g;
                float2 bp = *(const float2*)&Bs[n * 44 + kb + tg * 2];  // pair-packed
                bfr[nj][0] = __float_as_uint(bp.x);
                bfr[nj][1] = __float_as_uint(bp.y);
            }
#pragma unroll
            for (int mi = 0; mi < 4; mi++)
#pragma unroll
                for (int nj = 0; nj < 5; nj++)
                    mma_tf32(acc[mi][nj], afr[mi], bfr[nj]);
        }
    }
#undef STAGE

#pragma unroll
    for (int mi = 0; mi < 4; mi++) {
        int mrow = m0 + wm * 64 + mi * 16 + g;
#pragma unroll
        for (int nj = 0; nj < 5; nj++) {
            int ncol = n0 + wn * 40 + nj * 8 + 2 * tg;
            float bx = bc[ncol], by = bc[ncol + 1];
            *(float2*)(d_g + (size_t)mrow * G16 + ncol) =
                make_float2(acc[mi][nj][0] + bx, acc[mi][nj][1] + by);
            *(float2*)(d_g + (size_t)(mrow + 8) * G16 + ncol) =
                make_float2(acc[mi][nj][2] + bx, acc[mi][nj][3] + by);
        }
    }
}

// ---------------- persistent tensor-core bidirectional LSTM (R12 proven) ---
// 100 blocks = 2 dir x 2 batch-halves x 25 u-slices. 128 thr (4 warps).
// Sync: per-lane REDG counters. d_h k-pair-packed. MUFU activations.
#define NDB 25

__global__ __launch_bounds__(128, 1)
void lstm_layer(const float* __restrict__ Whhf, const float* __restrict__ Whhb, int layer) {
    extern __shared__ float sm[];
    float* hs = sm;            // [64][212] = 13568 floats
    float* Wp = sm + 13568;    // [32][206] = 6592 floats

    const int tid = threadIdx.x;
    const int lane = tid & 31, w = tid >> 5;   // w in 0..3
    const int bx = blockIdx.x;
    const int dir = bx / (2 * NDB);
    const int mh  = (bx / NDB) & 1;
    const int us  = bx % NDB;
    const int u0  = us * 8;
    const float* Whh = dir ? Whhb : Whhf;
    float* out = layer ? d_rnn : d_x1;
    float* hbuf0 = d_h[layer][dir][0];
    float* hbuf1 = d_h[layer][dir][1];

    // pack W_hh slice, tf32, pair-packed for float2 B-fragment loads
    for (int i = tid; i < 32 * 200; i += 128) {
        int n = i / 200, p = i % 200;
        int k0 = p >> 3, r = p & 7, tg2 = r >> 1, c = r & 1;
        int k = k0 * 8 + tg2 + 4 * c;
        int grow = (n >> 3) * Hh + u0 + (n & 7);
        Wp[n * 206 + p] = to_tf32(Whh[(size_t)grow * Hh + k]);
    }
    __syncthreads();

    const int m0 = mh * 64 + w * 16;   // global batch base for this warp
    const int lr0 = w * 16;            // local hs row base
    const int g = lane >> 2, tg = lane & 3;
    unsigned* bar = d_barc[layer] + (((dir * 2 + mh) * 4 + w) * 32);
    const uint32_t hs_base = (uint32_t)__cvta_generic_to_shared(hs);

    // packed positions (within 8-group) for this lane's two hidden units
    const int pu0 = (((2 * tg) & 3) << 1) | ((2 * tg) >> 2);          // u = u0+2tg
    const int pu1 = (((2 * tg + 1) & 3) << 1) | ((2 * tg + 1) >> 2);  // u = u0+2tg+1

    float cst[4] = {0.f, 0.f, 0.f, 0.f};
    float hreg[4] = {0.f, 0.f, 0.f, 0.f};

    // prefetch gates + mask for step 0
    float2 gx[4][2];
    float mk0, mk1;
    {
        int t0 = dir ? Tt - 1 : 0;
#pragma unroll
        for (int j = 0; j < 4; j++) {
            gx[j][0] = *(const float2*)&d_g[(size_t)((m0 + g) * Tt + t0) * G16 +
                                            dir * 800 + j * 200 + u0 + 2 * tg];
            gx[j][1] = *(const float2*)&d_g[(size_t)((m0 + g + 8) * Tt + t0) * G16 +
                                            dir * 800 + j * 200 + u0 + 2 * tg];
        }
        mk0 = d_mt[t0 * Bsz + m0 + g];
        mk1 = d_mt[t0 * Bsz + m0 + g + 8];
    }

    for (int s = 0; s < Tt; s++) {
        const int t = dir ? (Tt - 1 - s) : s;
        const float* hcur = (s & 1) ? hbuf1 : hbuf0;
        float* hnxt = (s & 1) ? hbuf0 : hbuf1;

        // wait for all 25 blocks of this warp-group to finish step s-1
        if (s) {
            unsigned tgt = (unsigned)NDB * (unsigned)s;
            while (ld_acq(&bar[lane]) < tgt) {}
        }
        __syncwarp();

        // bulk-stage this warp's 16 batch rows of h_prev (L1-bypassed)
        for (int i = lane; i < 800; i += 32) {
            int r16 = i / 50, c4 = (i % 50) * 4;
            cp16(hs_base + (uint32_t)((lr0 + r16) * 212 + c4) * 4,
                 hcur + (size_t)(m0 + r16) * Hh + c4);
        }
        asm volatile("cp.async.commit_group;");
        asm volatile("cp.async.wait_group 0;");
        __syncwarp();

        float acc[4][4];
#pragma unroll
        for (int j = 0; j < 4; j++)
#pragma unroll
            for (int r = 0; r < 4; r++) acc[j][r] = 0.f;

#pragma unroll
        for (int ik = 0; ik < 25; ik++) {
            const int kb = ik * 8;
            uint32_t a[4];
            {
                float2 f0 = *(const float2*)&hs[(lr0 + g) * 212 + kb + tg * 2];      // packed
                float2 f1 = *(const float2*)&hs[(lr0 + g + 8) * 212 + kb + tg * 2];
                a[0] = __float_as_uint(f0.x);
                a[1] = __float_as_uint(f1.x);
                a[2] = __float_as_uint(f0.y);
                a[3] = __float_as_uint(f1.y);
            }
#pragma unroll
            for (int j = 0; j < 4; j++) {
                float2 bp = *(const float2*)&Wp[(j * 8 + g) * 206 + kb + tg * 2];
                uint32_t bb[2] = { __float_as_uint(bp.x), __float_as_uint(bp.y) };
                mma_tf32(acc[j], a, bb);
            }
        }

#pragma unroll
        for (int j = 0; j < 4; j++) {
            acc[j][0] += gx[j][0].x; acc[j][1] += gx[j][0].y;
            acc[j][2] += gx[j][1].x; acc[j][3] += gx[j][1].y;
        }

        // cell update in registers (MUFU.TANH path)
        float ho[4];
#pragma unroll
        for (int r = 0; r < 4; r++) {
            float m = (r >> 1) ? mk1 : mk0;
            float iv = sig_(acc[0][r]);
            float fv = sig_(acc[1][r]);
            float gv = tanh_(acc[2][r]);
            float ov = sig_(acc[3][r]);
            float cn = fv * cst[r] + iv * gv;
            float hn = ov * tanh_(cn);
            float hnew = m * hn + (1.f - m) * hreg[r];
            cst[r] = m * cn + (1.f - m) * cst[r];
            hreg[r] = hnew;
            ho[r] = m * hn;
        }

        // store h_next (tf32, k-pair-packed positions)
        hnxt[(size_t)(m0 + g) * Hh + u0 + pu0]     = to_tf32(hreg[0]);
        hnxt[(size_t)(m0 + g) * Hh + u0 + pu1]     = to_tf32(hreg[1]);
        hnxt[(size_t)(m0 + g + 8) * Hh + u0 + pu0] = to_tf32(hreg[2]);
        hnxt[(size_t)(m0 + g + 8) * Hh + u0 + pu1] = to_tf32(hreg[3]);

        // release: each lane orders its own stores (spread-address REDG)
        red_rel(&bar[lane]);

        // ---- tail (off other blocks' critical path) ----
        {
            float2 o0 = make_float2(layer ? ho[0] : to_tf32(ho[0]),
                                    layer ? ho[1] : to_tf32(ho[1]));
            float2 o1 = make_float2(layer ? ho[2] : to_tf32(ho[2]),
                                    layer ? ho[3] : to_tf32(ho[3]));
            *(float2*)&out[(size_t)((m0 + g) * Tt + t) * IN1 + dir * Hh + u0 + 2 * tg] = o0;
            *(float2*)&out[(size_t)((m0 + g + 8) * Tt + t) * IN1 + dir * Hh + u0 + 2 * tg] = o1;
        }
        if (layer && s == Tt - 1) {
            *(float2*)&d_hfin[dir][(m0 + g) * Hh + u0 + 2 * tg] =
                make_float2(hreg[0], hreg[1]);
            *(float2*)&d_hfin[dir][(m0 + g + 8) * Hh + u0 + 2 * tg] =
                make_float2(hreg[2], hreg[3]);
        }
        if (s < Tt - 1) {
            int tn = dir ? (Tt - 2 - s) : (s + 1);
#pragma unroll
            for (int j = 0; j < 4; j++) {
                gx[j][0] = *(const float2*)&d_g[(size_t)((m0 + g) * Tt + tn) * G16 +
                                                dir * 800 + j * 200 + u0 + 2 * tg];
                gx[j][1] = *(const float2*)&d_g[(size_t)((m0 + g + 8) * Tt + tn) * G16 +
                                                dir * 800 + j * 200 + u0 + 2 * tg];
            }
            mk0 = d_mt[tn * Bsz + m0 + g];
            mk1 = d_mt[tn * Bsz + m0 + g + 8];
        }
    }
}

// ---------------- fused pool: span sums + 3x attention ----------------------
__global__ __launch_bounds__(256)
void pool_kernel(const int* __restrict__ masks, const int* __restrict__ subj,
                 const int* __restrict__ obj) {
    int b = blockIdx.x;
    __shared__ float ssel[Tt];
    __shared__ float osel[Tt];
    __shared__ float qv[3][IN1];     // 0=obj_h 1=subj_h 2=glob_h
    __shared__ float ps[3][Tt];
    __shared__ float red[256];
    int tid = threadIdx.x, lane = tid & 31, w = tid >> 5;

    for (int t = tid; t < Tt; t += 256) {
        int m = masks[b * Tt + t];
        ssel[t] = (subj[b * Tt + t] + m == 0) ? 1.f : 0.f;
        osel[t] = (obj[b * Tt + t] + m == 0) ? 1.f : 0.f;
    }
    __syncthreads();

    for (int f = tid; f < IN1; f += 256) {
        float ss = 0.f, os = 0.f;
        for (int t = 0; t < Tt; t++) {
            float v = d_rnn[(size_t)(b * Tt + t) * IN1 + f];
            ss += v * ssel[t];
            os += v * osel[t];
        }
        qv[0][f] = os;
        qv[1][f] = ss;
        qv[2][f] = (f < Hh) ? d_hfin[1][b * Hh + f] : d_hfin[0][b * Hh + f - Hh];
    }
    __syncthreads();

    for (int t = w; t < Tt; t += 8) {
        const float* row = d_rnn + (size_t)(b * Tt + t) * IN1;
        float s0 = 0.f, s1 = 0.f, s2 = 0.f;
        for (int k = lane; k < IN1; k += 32) {
            float v = row[k];
            s0 += qv[0][k] * v;
            s1 += qv[1][k] * v;
            s2 += qv[2][k] * v;
        }
        for (int o = 16; o; o >>= 1) {
            s0 += __shfl_down_sync(0xffffffffu, s0, o);
            s1 += __shfl_down_sync(0xffffffffu, s1, o);
            s2 += __shfl_down_sync(0xffffffffu, s2, o);
        }
        if (lane == 0) {
            ps[0][t] = s0 * 0.05f;
            ps[1][t] = s1 * 0.05f;
            ps[2][t] = s2 * 0.05f;
        }
    }
    __syncthreads();

    {
        bool pad = masks[b * Tt + tid] != 0;
        if (pad) { ps[0][tid] = -1e9f; ps[1][tid] = -1e9f; ps[2][tid] = -1e9f; }
    }
    __syncthreads();

#pragma unroll
    for (int qi = 0; qi < 3; qi++) {
        float sc = ps[qi][tid];
        red[tid] = sc; __syncthreads();
        for (int o = 128; o; o >>= 1) { if (tid < o) red[tid] = fmaxf(red[tid], red[tid + o]); __syncthreads(); }
        float mx = red[0]; __syncthreads();
        float e = __expf(sc - mx);
        red[tid] = e; __syncthreads();
        for (int o = 128; o; o >>= 1) { if (tid < o) red[tid] += red[tid + o]; __syncthreads(); }
        float inv = 1.f / red[0];
        __syncthreads();
        ps[qi][tid] = e * inv;
        __syncthreads();
    }

    for (int f = tid; f < IN1; f += 256) {
        float a0 = 0.f, a1 = 0.f, a2 = 0.f;
        for (int t = 0; t < Tt; t++) {
            float v = d_rnn[(size_t)(b * Tt + t) * IN1 + f];
            a0 += ps[0][t] * v;
            a1 += ps[1][t] * v;
            a2 += ps[2][t] * v;
        }
        d_att[0][b * IN1 + f] = a0;
        d_att[1][b * IN1 + f] = a1;
        d_att[2][b * IN1 + f] = a2;
    }
}

// ---------------- final MLP head ----------------
__global__ void final_kernel(const float* __restrict__ wo_w, const float* __restrict__ wo_b,
                             const float* __restrict__ ws_w, const float* __restrict__ ws_b,
                             const float* __restrict__ wg_w, const float* __restrict__ wg_b,
                             const float* __restrict__ cls_w, const float* __restrict__ cls_b,
                             float* __restrict__ outp) {
    int b = blockIdx.x;
    __shared__ float hv[Hh];
    int j = threadIdx.x;
    if (j < Hh) {
        float a = wo_b[j] + ws_b[j] + wg_b[j];
        const float* o = &d_att[0][b * IN1];
        const float* s = &d_att[1][b * IN1];
        const float* gq = &d_att[2][b * IN1];
        const float* wo = wo_w + (size_t)j * IN1;
        const float* ws = ws_w + (size_t)j * IN1;
        const float* wg = wg_w + (size_t)j * IN1;
        for (int k = 0; k < IN1; k++)
            a += o[k] * wo[k] + s[k] * ws[k] + gq[k] * wg[k];
        hv[j] = fmaxf(a, 0.f);
    }
    __syncthreads();
    if (j < 64) {
        int n = j >> 5, lane = j & 31;
        float p = 0.f;
        for (int k = lane; k < Hh; k += 32) p += hv[k] * cls_w[n * Hh + k];
        for (int o = 16; o; o >>= 1) p += __shfl_down_sync(0xffffffffu, p, o);
        if (lane == 0) outp[b * NCLASS + n] = p + cls_b[n];
    }
}

// ---------------- launcher ----------------
extern "C" void kernel_launch(void* const* d_in, const int* in_sizes, int n_in,
                              void* d_out, int out_size) {
    const int*   words    = (const int*)d_in[0];
    const int*   masks    = (const int*)d_in[1];
    const int*   pos      = (const int*)d_in[2];
    const int*   ner      = (const int*)d_in[3];
    const int*   subj_pos = (const int*)d_in[4];
    const int*   obj_pos  = (const int*)d_in[5];
    const float* emb_w    = (const float*)d_in[6];
    const float* pos_w    = (const float*)d_in[7];
    const float* ner_w    = (const float*)d_in[8];
    const float* w_ih_l0f = (const float*)d_in[9];
    const float* w_hh_l0f = (const float*)d_in[10];
    const float* b_l0f    = (const float*)d_in[11];
    const float* w_ih_l0b = (const float*)d_in[12];
    const float* w_hh_l0b = (const float*)d_in[13];
    const float* b_l0b    = (const float*)d_in[14];
    const float* w_ih_l1f = (const float*)d_in[15];
    const float* w_hh_l1f = (const float*)d_in[16];
    const float* b_l1f    = (const float*)d_in[17];
    const float* w_ih_l1b = (const float*)d_in[18];
    const float* w_hh_l1b = (const float*)d_in[19];
    const float* b_l1b    = (const float*)d_in[20];
    const float* wo_w     = (const float*)d_in[21];
    const float* wo_b     = (const float*)d_in[22];
    const float* ws_w     = (const float*)d_in[23];
    const float* ws_b     = (const float*)d_in[24];
    const float* wg_w     = (const float*)d_in[25];
    const float* wg_b     = (const float*)d_in[26];
    const float* cls_w    = (const float*)d_in[27];
    const float* cls_b    = (const float*)d_in[28];

    static const int GEMM_SMEM = 3 * GSTG * 4;   // 152064 B
    static const int LSTM_SMEM = 20160 * 4;      // 80640 B
    cudaFuncSetAttribute(gemm_tf32, cudaFuncAttributeMaxDynamicSharedMemorySize, GEMM_SMEM);
    cudaFuncSetAttribute(lstm_layer, cudaFuncAttributeMaxDynamicSharedMemorySize, LSTM_SMEM);

    dim3 ggrid(10, 256);   // N=1600/160, M=32768/128

    embedprep_kernel<<<(BT * 400 + 255) / 256, 256>>>(
        words, pos, ner, emb_w, pos_w, ner_w,
        w_ih_l0f, w_ih_l0b, b_l0f, b_l0b,
        w_ih_l1f, w_ih_l1b, b_l1f, b_l1b, masks);                                        // 0
    gemm_tf32<<<ggrid, 256, GEMM_SMEM>>>(0, 0);                                           // 1
    lstm_layer<<<4 * NDB, 128, LSTM_SMEM>>>(w_hh_l0f, w_hh_l0b, 0);                       // 2
    gemm_tf32<<<ggrid, 256, GEMM_SMEM>>>(1, 1);                                           // 3
    lstm_layer<<<4 * NDB, 128, LSTM_SMEM>>>(w_hh_l1f, w_hh_l1b, 1);                       // 4
    pool_kernel<<<Bsz, 256>>>(masks, subj_pos, obj_pos);                                  // 5
    final_kernel<<<Bsz, 256>>>(wo_w, wo_b, ws_w, ws_b, wg_w, wg_b, cls_w, cls_b,
                               (float*)d_out);                                            // 6
}

// round 14
// speedup vs baseline: 1.2429x; 1.0108x over previous
#include <cuda_runtime.h>
#include <cstdint>

#define Bsz 128
#define Tt 256
#define Hh 200
#define IN1 400
#define BT (Bsz*Tt)
#define NCLASS 2
#define G16 1600

// ---------------- device scratch (static, no allocation) ----------------
__device__ __align__(16) float d_x0[BT*400];        // embeddings, tf32, natural layout
__device__ __align__(16) float d_x1[BT*400];        // layer0 output (tf32, natural)
__device__ __align__(16) float d_rnn[BT*400];       // layer1 output (fp32, natural)
__device__ __align__(16) float d_g[(size_t)BT*G16]; // gates: [bt][fwd 800 | bwd 800]
__device__ __align__(16) float d_h[2][2][2][Bsz*Hh];// [layer][dir][buf][b*200+u] packed
__device__ __align__(16) float d_hfin[2][Bsz*Hh];   // natural
__device__ __align__(16) float d_att[3][Bsz*IN1];
__device__ __align__(16) float d_wcat[2][G16*400];  // padded tf32 W_ih, k pair-packed
__device__ __align__(16) float d_bcat[2][G16];
__device__ __align__(16) float d_mt[Tt*Bsz];        // keep-mask transposed [t][b]
__device__ unsigned d_barc[2][512];                 // per-layer: 16 groups x 32 counters

// ---------------- helpers ----------------
__device__ __forceinline__ float tanh_(float x) {
    float r;
    asm("tanh.approx.f32 %0, %1;" : "=f"(r) : "f"(x));
    return r;
}
__device__ __forceinline__ float sig_(float x) {
    return fmaf(tanh_(0.5f * x), 0.5f, 0.5f);
}
__device__ __forceinline__ float to_tf32(float x) {
    float r;
    asm("cvt.rna.tf32.f32 %0, %1;" : "=f"(r) : "f"(x));
    return r;
}
__device__ __forceinline__ void mma_tf32(float* d, const uint32_t* a, const uint32_t* b) {
    asm volatile(
        "mma.sync.aligned.m16n8k8.row.col.f32.tf32.tf32.f32 "
        "{%0,%1,%2,%3}, {%4,%5,%6,%7}, {%8,%9}, {%0,%1,%2,%3};"
        : "+f"(d[0]), "+f"(d[1]), "+f"(d[2]), "+f"(d[3])
        : "r"(a[0]), "r"(a[1]), "r"(a[2]), "r"(a[3]), "r"(b[0]), "r"(b[1]));
}
__device__ __forceinline__ void cp16(uint32_t saddr, const void* gaddr) {
    asm volatile("cp.async.cg.shared.global [%0], [%1], 16;" :: "r"(saddr), "l"(gaddr));
}
__device__ __forceinline__ unsigned ld_acq(const unsigned* p) {
    unsigned v;
    asm volatile("ld.acquire.gpu.global.u32 %0, [%1];" : "=r"(v) : "l"(p) : "memory");
    return v;
}
__device__ __forceinline__ void red_rel(unsigned* p) {
    asm volatile("red.release.gpu.global.add.u32 [%0], %1;" :: "l"(p), "r"(1u) : "memory");
}

// ---------------- fused embed + prep (also zeroes both layers' h + counters)
__global__ void embedprep_kernel(const int* __restrict__ words, const int* __restrict__ pos,
                                 const int* __restrict__ ner,
                                 const float* __restrict__ emb_w, const float* __restrict__ pos_w,
                                 const float* __restrict__ ner_w,
                                 const float* __restrict__ wf0, const float* __restrict__ wb0,
                                 const float* __restrict__ bf0, const float* __restrict__ bb0,
                                 const float* __restrict__ wf1, const float* __restrict__ wb1,
                                 const float* __restrict__ bf1, const float* __restrict__ bb1,
                                 const int* __restrict__ masks) {
    int i = blockIdx.x * blockDim.x + threadIdx.x;
    if (i < BT * 400) {
        int c = i % 400, bt = i / 400;
        float v = 0.f;
        if (c < 300)        v = emb_w[(size_t)words[bt] * 300 + c];
        else if (c < 330)   v = pos_w[(size_t)pos[bt] * 30 + (c - 300)];
        else if (c < 360)   v = ner_w[(size_t)ner[bt] * 30 + (c - 330)];
        d_x0[i] = to_tf32(v);
    }
    if (i < G16 * 400) {
        int n = i / 400, p = i % 400;
        int k0 = p >> 3, r = p & 7, tg = r >> 1, c = r & 1;
        int k = k0 * 8 + tg + 4 * c;
        int nn = (n < 800) ? n : n - 800;
        float v0 = 0.f, v1 = 0.f;
        if (k < 360) {
            const float* W = (n < 800) ? wf0 : wb0;
            v0 = to_tf32(W[(size_t)nn * 360 + k]);
        }
        {
            const float* W = (n < 800) ? wf1 : wb1;
            v1 = to_tf32(W[(size_t)nn * 400 + k]);
        }
        d_wcat[0][i] = v0;
        d_wcat[1][i] = v1;
    }
    if (i < G16) {
        d_bcat[0][i] = (i < 800) ? bf0[i] : bb0[i - 800];
        d_bcat[1][i] = (i < 800) ? bf1[i] : bb1[i - 800];
    }
    if (i < Tt * Bsz) {
        int t = i / Bsz, b = i % Bsz;
        d_mt[i] = (masks[b * Tt + t] == 0) ? 1.f : 0.f;
    }
    if (i < 2 * 2 * 2 * Bsz * Hh) ((float*)d_h)[i] = 0.f;
    if (i < 2 * 512) ((unsigned*)d_barc)[i] = 0;
}

// ---------------- TF32 GEMM: d_g[32768,1600] = A[32768,400] @ Wcat^T + bias -
// 384 threads, 12 warps (3 m x 4 n), warp tile 64x40, BM=192, BN=160, BK=40,
// 3-stage cp.async ring, B k-pair-packed (LDS.64 fragments).
// 3 warps/SMSP for latency hiding (vs 2 at 256 thr). Ragged M edge guarded.
#define GBM 192
#define GSTG 15488   // floats per stage: A 192*44 + B 160*44

__global__ __launch_bounds__(384, 1)
void gemm_tf32(int asel, int layer) {
    extern __shared__ float smg[];
    const float* A = asel ? d_x1 : d_x0;
    const float* Wc = d_wcat[layer];
    const float* bc = d_bcat[layer];

    const int tid = threadIdx.x;
    const int lane = tid & 31, w = tid >> 5;
    const int wm = w % 3, wn = w / 3;           // 3 x 4 warp grid
    const int g = lane >> 2, tg = lane & 3;
    const int m0 = blockIdx.y * GBM, n0 = blockIdx.x * 160;

    const uint32_t sbase = (uint32_t)__cvta_generic_to_shared(smg);

    float acc[4][5][4];
#pragma unroll
    for (int i = 0; i < 4; i++)
#pragma unroll
        for (int j = 0; j < 5; j++)
#pragma unroll
            for (int r = 0; r < 4; r++) acc[i][j][r] = 0.f;

#define STAGE(IT, S) do {                                                      \
        int k0 = (IT) * 40;                                                    \
        uint32_t aB = sbase + (uint32_t)((S) * GSTG) * 4;                      \
        uint32_t bB = aB + 8448u * 4u;                                         \
        for (int i = tid; i < 1920; i += 384) {                                \
            int row = i / 10, c4 = (i % 10) * 4;                               \
            if (m0 + row < BT)                                                 \
                cp16(aB + (uint32_t)(row * 44 + c4) * 4,                       \
                     A + (size_t)(m0 + row) * 400 + k0 + c4);                  \
        }                                                                      \
        for (int i = tid; i < 1600; i += 384) {                                \
            int row = i / 10, c4 = (i % 10) * 4;                               \
            cp16(bB + (uint32_t)(row * 44 + c4) * 4,                           \
                 Wc + (size_t)(n0 + row) * 400 + k0 + c4);                     \
        }                                                                      \
        asm volatile("cp.async.commit_group;");                                \
    } while (0)

    STAGE(0, 0);
    STAGE(1, 1);

    for (int it = 0; it < 10; it++) {
        asm volatile("cp.async.wait_group 1;");
        __syncthreads();
        if (it + 2 < 10) STAGE(it + 2, (it + 2) % 3);

        const float* As = smg + (it % 3) * GSTG;
        const float* Bs = As + 8448;
#pragma unroll
        for (int ks = 0; ks < 5; ks++) {
            const int kb = ks * 8;
            uint32_t afr[4][4];
#pragma unroll
            for (int mi = 0; mi < 4; mi++) {
                int m = wm * 64 + mi * 16 + g;
                afr[mi][0] = __float_as_uint(As[m * 44 + kb + tg]);
                afr[mi][1] = __float_as_uint(As[(m + 8) * 44 + kb + tg]);
                afr[mi][2] = __float_as_uint(As[m * 44 + kb + tg + 4]);
                afr[mi][3] = __float_as_uint(As[(m + 8) * 44 + kb + tg + 4]);
            }
            uint32_t bfr[5][2];
#pragma unroll
            for (int nj = 0; nj < 5; nj++) {
                int n = wn * 40 + nj * 8 + g;
                float2 bp = *(const float2*)&Bs[n * 44 + kb + tg * 2];  // pair-packed
                bfr[nj][0] = __float_as_uint(bp.x);
                bfr[nj][1] = __float_as_uint(bp.y);
            }
#pragma unroll
            for (int mi = 0; mi < 4; mi++)
#pragma unroll
                for (int nj = 0; nj < 5; nj++)
                    mma_tf32(acc[mi][nj], afr[mi], bfr[nj]);
        }
    }
#undef STAGE

#pragma unroll
    for (int mi = 0; mi < 4; mi++) {
        int mrow = m0 + wm * 64 + mi * 16 + g;
        if (mrow + 8 < BT) {
#pragma unroll
            for (int nj = 0; nj < 5; nj++) {
                int ncol = n0 + wn * 40 + nj * 8 + 2 * tg;
                float bx = bc[ncol], by = bc[ncol + 1];
                *(float2*)(d_g + (size_t)mrow * G16 + ncol) =
                    make_float2(acc[mi][nj][0] + bx, acc[mi][nj][1] + by);
                *(float2*)(d_g + (size_t)(mrow + 8) * G16 + ncol) =
                    make_float2(acc[mi][nj][2] + bx, acc[mi][nj][3] + by);
            }
        }
    }
}

// ---------------- persistent tensor-core bidirectional LSTM (R12 proven) ---
// 100 blocks = 2 dir x 2 batch-halves x 25 u-slices. 128 thr (4 warps).
// Sync: per-lane REDG counters. d_h k-pair-packed. MUFU activations.
#define NDB 25

__global__ __launch_bounds__(128, 1)
void lstm_layer(const float* __restrict__ Whhf, const float* __restrict__ Whhb, int layer) {
    extern __shared__ float sm[];
    float* hs = sm;            // [64][212] = 13568 floats
    float* Wp = sm + 13568;    // [32][206] = 6592 floats

    const int tid = threadIdx.x;
    const int lane = tid & 31, w = tid >> 5;   // w in 0..3
    const int bx = blockIdx.x;
    const int dir = bx / (2 * NDB);
    const int mh  = (bx / NDB) & 1;
    const int us  = bx % NDB;
    const int u0  = us * 8;
    const float* Whh = dir ? Whhb : Whhf;
    float* out = layer ? d_rnn : d_x1;
    float* hbuf0 = d_h[layer][dir][0];
    float* hbuf1 = d_h[layer][dir][1];

    // pack W_hh slice, tf32, pair-packed for float2 B-fragment loads
    for (int i = tid; i < 32 * 200; i += 128) {
        int n = i / 200, p = i % 200;
        int k0 = p >> 3, r = p & 7, tg2 = r >> 1, c = r & 1;
        int k = k0 * 8 + tg2 + 4 * c;
        int grow = (n >> 3) * Hh + u0 + (n & 7);
        Wp[n * 206 + p] = to_tf32(Whh[(size_t)grow * Hh + k]);
    }
    __syncthreads();

    const int m0 = mh * 64 + w * 16;   // global batch base for this warp
    const int lr0 = w * 16;            // local hs row base
    const int g = lane >> 2, tg = lane & 3;
    unsigned* bar = d_barc[layer] + (((dir * 2 + mh) * 4 + w) * 32);
    const uint32_t hs_base = (uint32_t)__cvta_generic_to_shared(hs);

    // packed positions (within 8-group) for this lane's two hidden units
    const int pu0 = (((2 * tg) & 3) << 1) | ((2 * tg) >> 2);          // u = u0+2tg
    const int pu1 = (((2 * tg + 1) & 3) << 1) | ((2 * tg + 1) >> 2);  // u = u0+2tg+1

    float cst[4] = {0.f, 0.f, 0.f, 0.f};
    float hreg[4] = {0.f, 0.f, 0.f, 0.f};

    // prefetch gates + mask for step 0
    float2 gx[4][2];
    float mk0, mk1;
    {
        int t0 = dir ? Tt - 1 : 0;
#pragma unroll
        for (int j = 0; j < 4; j++) {
            gx[j][0] = *(const float2*)&d_g[(size_t)((m0 + g) * Tt + t0) * G16 +
                                            dir * 800 + j * 200 + u0 + 2 * tg];
            gx[j][1] = *(const float2*)&d_g[(size_t)((m0 + g + 8) * Tt + t0) * G16 +
                                            dir * 800 + j * 200 + u0 + 2 * tg];
        }
        mk0 = d_mt[t0 * Bsz + m0 + g];
        mk1 = d_mt[t0 * Bsz + m0 + g + 8];
    }

    for (int s = 0; s < Tt; s++) {
        const int t = dir ? (Tt - 1 - s) : s;
        const float* hcur = (s & 1) ? hbuf1 : hbuf0;
        float* hnxt = (s & 1) ? hbuf0 : hbuf1;

        // wait for all 25 blocks of this warp-group to finish step s-1
        if (s) {
            unsigned tgt = (unsigned)NDB * (unsigned)s;
            while (ld_acq(&bar[lane]) < tgt) {}
        }
        __syncwarp();

        // bulk-stage this warp's 16 batch rows of h_prev (L1-bypassed)
        for (int i = lane; i < 800; i += 32) {
            int r16 = i / 50, c4 = (i % 50) * 4;
            cp16(hs_base + (uint32_t)((lr0 + r16) * 212 + c4) * 4,
                 hcur + (size_t)(m0 + r16) * Hh + c4);
        }
        asm volatile("cp.async.commit_group;");
        asm volatile("cp.async.wait_group 0;");
        __syncwarp();

        float acc[4][4];
#pragma unroll
        for (int j = 0; j < 4; j++)
#pragma unroll
            for (int r = 0; r < 4; r++) acc[j][r] = 0.f;

#pragma unroll
        for (int ik = 0; ik < 25; ik++) {
            const int kb = ik * 8;
            uint32_t a[4];
            {
                float2 f0 = *(const float2*)&hs[(lr0 + g) * 212 + kb + tg * 2];      // packed
                float2 f1 = *(const float2*)&hs[(lr0 + g + 8) * 212 + kb + tg * 2];
                a[0] = __float_as_uint(f0.x);
                a[1] = __float_as_uint(f1.x);
                a[2] = __float_as_uint(f0.y);
                a[3] = __float_as_uint(f1.y);
            }
#pragma unroll
            for (int j = 0; j < 4; j++) {
                float2 bp = *(const float2*)&Wp[(j * 8 + g) * 206 + kb + tg * 2];
                uint32_t bb[2] = { __float_as_uint(bp.x), __float_as_uint(bp.y) };
                mma_tf32(acc[j], a, bb);
            }
        }

#pragma unroll
        for (int j = 0; j < 4; j++) {
            acc[j][0] += gx[j][0].x; acc[j][1] += gx[j][0].y;
            acc[j][2] += gx[j][1].x; acc[j][3] += gx[j][1].y;
        }

        // cell update in registers (MUFU.TANH path)
        float ho[4];
#pragma unroll
        for (int r = 0; r < 4; r++) {
            float m = (r >> 1) ? mk1 : mk0;
            float iv = sig_(acc[0][r]);
            float fv = sig_(acc[1][r]);
            float gv = tanh_(acc[2][r]);
            float ov = sig_(acc[3][r]);
            float cn = fv * cst[r] + iv * gv;
            float hn = ov * tanh_(cn);
            float hnew = m * hn + (1.f - m) * hreg[r];
            cst[r] = m * cn + (1.f - m) * cst[r];
            hreg[r] = hnew;
            ho[r] = m * hn;
        }

        // store h_next (tf32, k-pair-packed positions)
        hnxt[(size_t)(m0 + g) * Hh + u0 + pu0]     = to_tf32(hreg[0]);
        hnxt[(size_t)(m0 + g) * Hh + u0 + pu1]     = to_tf32(hreg[1]);
        hnxt[(size_t)(m0 + g + 8) * Hh + u0 + pu0] = to_tf32(hreg[2]);
        hnxt[(size_t)(m0 + g + 8) * Hh + u0 + pu1] = to_tf32(hreg[3]);

        // release: each lane orders its own stores (spread-address REDG)
        red_rel(&bar[lane]);

        // ---- tail (off other blocks' critical path) ----
        {
            float2 o0 = make_float2(layer ? ho[0] : to_tf32(ho[0]),
                                    layer ? ho[1] : to_tf32(ho[1]));
            float2 o1 = make_float2(layer ? ho[2] : to_tf32(ho[2]),
                                    layer ? ho[3] : to_tf32(ho[3]));
            *(float2*)&out[(size_t)((m0 + g) * Tt + t) * IN1 + dir * Hh + u0 + 2 * tg] = o0;
            *(float2*)&out[(size_t)((m0 + g + 8) * Tt + t) * IN1 + dir * Hh + u0 + 2 * tg] = o1;
        }
        if (layer && s == Tt - 1) {
            *(float2*)&d_hfin[dir][(m0 + g) * Hh + u0 + 2 * tg] =
                make_float2(hreg[0], hreg[1]);
            *(float2*)&d_hfin[dir][(m0 + g + 8) * Hh + u0 + 2 * tg] =
                make_float2(hreg[2], hreg[3]);
        }
        if (s < Tt - 1) {
            int tn = dir ? (Tt - 2 - s) : (s + 1);
#pragma unroll
            for (int j = 0; j < 4; j++) {
                gx[j][0] = *(const float2*)&d_g[(size_t)((m0 + g) * Tt + tn) * G16 +
                                                dir * 800 + j * 200 + u0 + 2 * tg];
                gx[j][1] = *(const float2*)&d_g[(size_t)((m0 + g + 8) * Tt + tn) * G16 +
                                                dir * 800 + j * 200 + u0 + 2 * tg];
            }
            mk0 = d_mt[tn * Bsz + m0 + g];
            mk1 = d_mt[tn * Bsz + m0 + g + 8];
        }
    }
}

// ---------------- fused pool: span sums + 3x attention ----------------------
__global__ __launch_bounds__(256)
void pool_kernel(const int* __restrict__ masks, const int* __restrict__ subj,
                 const int* __restrict__ obj) {
    int b = blockIdx.x;
    __shared__ float ssel[Tt];
    __shared__ float osel[Tt];
    __shared__ float qv[3][IN1];     // 0=obj_h 1=subj_h 2=glob_h
    __shared__ float ps[3][Tt];
    __shared__ float red[256];
    int tid = threadIdx.x, lane = tid & 31, w = tid >> 5;

    for (int t = tid; t < Tt; t += 256) {
        int m = masks[b * Tt + t];
        ssel[t] = (subj[b * Tt + t] + m == 0) ? 1.f : 0.f;
        osel[t] = (obj[b * Tt + t] + m == 0) ? 1.f : 0.f;
    }
    __syncthreads();

    for (int f = tid; f < IN1; f += 256) {
        float ss = 0.f, os = 0.f;
        for (int t = 0; t < Tt; t++) {
            float v = d_rnn[(size_t)(b * Tt + t) * IN1 + f];
            ss += v * ssel[t];
            os += v * osel[t];
        }
        qv[0][f] = os;
        qv[1][f] = ss;
        qv[2][f] = (f < Hh) ? d_hfin[1][b * Hh + f] : d_hfin[0][b * Hh + f - Hh];
    }
    __syncthreads();

    for (int t = w; t < Tt; t += 8) {
        const float* row = d_rnn + (size_t)(b * Tt + t) * IN1;
        float s0 = 0.f, s1 = 0.f, s2 = 0.f;
        for (int k = lane; k < IN1; k += 32) {
            float v = row[k];
            s0 += qv[0][k] * v;
            s1 += qv[1][k] * v;
            s2 += qv[2][k] * v;
        }
        for (int o = 16; o; o >>= 1) {
            s0 += __shfl_down_sync(0xffffffffu, s0, o);
            s1 += __shfl_down_sync(0xffffffffu, s1, o);
            s2 += __shfl_down_sync(0xffffffffu, s2, o);
        }
        if (lane == 0) {
            ps[0][t] = s0 * 0.05f;
            ps[1][t] = s1 * 0.05f;
            ps[2][t] = s2 * 0.05f;
        }
    }
    __syncthreads();

    {
        bool pad = masks[b * Tt + tid] != 0;
        if (pad) { ps[0][tid] = -1e9f; ps[1][tid] = -1e9f; ps[2][tid] = -1e9f; }
    }
    __syncthreads();

#pragma unroll
    for (int qi = 0; qi < 3; qi++) {
        float sc = ps[qi][tid];
        red[tid] = sc; __syncthreads();
        for (int o = 128; o; o >>= 1) { if (tid < o) red[tid] = fmaxf(red[tid], red[tid + o]); __syncthreads(); }
        float mx = red[0]; __syncthreads();
        float e = __expf(sc - mx);
        red[tid] = e; __syncthreads();
        for (int o = 128; o; o >>= 1) { if (tid < o) red[tid] += red[tid + o]; __syncthreads(); }
        float inv = 1.f / red[0];
        __syncthreads();
        ps[qi][tid] = e * inv;
        __syncthreads();
    }

    for (int f = tid; f < IN1; f += 256) {
        float a0 = 0.f, a1 = 0.f, a2 = 0.f;
        for (int t = 0; t < Tt; t++) {
            float v = d_rnn[(size_t)(b * Tt + t) * IN1 + f];
            a0 += ps[0][t] * v;
            a1 += ps[1][t] * v;
            a2 += ps[2][t] * v;
        }
        d_att[0][b * IN1 + f] = a0;
        d_att[1][b * IN1 + f] = a1;
        d_att[2][b * IN1 + f] = a2;
    }
}

// ---------------- final MLP head ----------------
__global__ void final_kernel(const float* __restrict__ wo_w, const float* __restrict__ wo_b,
                             const float* __restrict__ ws_w, const float* __restrict__ ws_b,
                             const float* __restrict__ wg_w, const float* __restrict__ wg_b,
                             const float* __restrict__ cls_w, const float* __restrict__ cls_b,
                             float* __restrict__ outp) {
    int b = blockIdx.x;
    __shared__ float hv[Hh];
    int j = threadIdx.x;
    if (j < Hh) {
        float a = wo_b[j] + ws_b[j] + wg_b[j];
        const float* o = &d_att[0][b * IN1];
        const float* s = &d_att[1][b * IN1];
        const float* gq = &d_att[2][b * IN1];
        const float* wo = wo_w + (size_t)j * IN1;
        const float* ws = ws_w + (size_t)j * IN1;
        const float* wg = wg_w + (size_t)j * IN1;
        for (int k = 0; k < IN1; k++)
            a += o[k] * wo[k] + s[k] * ws[k] + gq[k] * wg[k];
        hv[j] = fmaxf(a, 0.f);
    }
    __syncthreads();
    if (j < 64) {
        int n = j >> 5, lane = j & 31;
        float p = 0.f;
        for (int k = lane; k < Hh; k += 32) p += hv[k] * cls_w[n * Hh + k];
        for (int o = 16; o; o >>= 1) p += __shfl_down_sync(0xffffffffu, p, o);
        if (lane == 0) outp[b * NCLASS + n] = p + cls_b[n];
    }
}

// ---------------- launcher ----------------
extern "C" void kernel_launch(void* const* d_in, const int* in_sizes, int n_in,
                              void* d_out, int out_size) {
    const int*   words    = (const int*)d_in[0];
    const int*   masks    = (const int*)d_in[1];
    const int*   pos      = (const int*)d_in[2];
    const int*   ner      = (const int*)d_in[3];
    const int*   subj_pos = (const int*)d_in[4];
    const int*   obj_pos  = (const int*)d_in[5];
    const float* emb_w    = (const float*)d_in[6];
    const float* pos_w    = (const float*)d_in[7];
    const float* ner_w    = (const float*)d_in[8];
    const float* w_ih_l0f = (const float*)d_in[9];
    const float* w_hh_l0f = (const float*)d_in[10];
    const float* b_l0f    = (const float*)d_in[11];
    const float* w_ih_l0b = (const float*)d_in[12];
    const float* w_hh_l0b = (const float*)d_in[13];
    const float* b_l0b    = (const float*)d_in[14];
    const float* w_ih_l1f = (const float*)d_in[15];
    const float* w_hh_l1f = (const float*)d_in[16];
    const float* b_l1f    = (const float*)d_in[17];
    const float* w_ih_l1b = (const float*)d_in[18];
    const float* w_hh_l1b = (const float*)d_in[19];
    const float* b_l1b    = (const float*)d_in[20];
    const float* wo_w     = (const float*)d_in[21];
    const float* wo_b     = (const float*)d_in[22];
    const float* ws_w     = (const float*)d_in[23];
    const float* ws_b     = (const float*)d_in[24];
    const float* wg_w     = (const float*)d_in[25];
    const float* wg_b     = (const float*)d_in[26];
    const float* cls_w    = (const float*)d_in[27];
    const float* cls_b    = (const float*)d_in[28];

    static const int GEMM_SMEM = 3 * GSTG * 4;   // 185856 B
    static const int LSTM_SMEM = 20160 * 4;      // 80640 B
    cudaFuncSetAttribute(gemm_tf32, cudaFuncAttributeMaxDynamicSharedMemorySize, GEMM_SMEM);
    cudaFuncSetAttribute(lstm_layer, cudaFuncAttributeMaxDynamicSharedMemorySize, LSTM_SMEM);

    dim3 ggrid(10, (BT + GBM - 1) / GBM);   // N=1600/160, M=32768/192 = 171

    embedprep_kernel<<<(BT * 400 + 255) / 256, 256>>>(
        words, pos, ner, emb_w, pos_w, ner_w,
        w_ih_l0f, w_ih_l0b, b_l0f, b_l0b,
        w_ih_l1f, w_ih_l1b, b_l1f, b_l1b, masks);                                        // 0
    gemm_tf32<<<ggrid, 384, GEMM_SMEM>>>(0, 0);                                           // 1
    lstm_layer<<<4 * NDB, 128, LSTM_SMEM>>>(w_hh_l0f, w_hh_l0b, 0);                       // 2
    gemm_tf32<<<ggrid, 384, GEMM_SMEM>>>(1, 1);                                           // 3
    lstm_layer<<<4 * NDB, 128, LSTM_SMEM>>>(w_hh_l1f, w_hh_l1b, 1);                       // 4
    pool_kernel<<<Bsz, 256>>>(masks, subj_pos, obj_pos);                                  // 5
    final_kernel<<<Bsz, 256>>>(wo_w, wo_b, ws_w, ws_b, wg_w, wg_b, cls_w, cls_b,
                               (float*)d_out);                                            // 6
}

// round 15
// speedup vs baseline: 1.2810x; 1.0306x over previous
#include <cuda_runtime.h>
#include <cstdint>

#define Bsz 128
#define Tt 256
#define Hh 200
#define IN1 400
#define BT (Bsz*Tt)
#define NCLASS 2
#define G16 1600

// ---------------- device scratch (static, no allocation) ----------------
__device__ __align__(16) float d_x0[BT*400];        // embeddings, tf32, natural layout
__device__ __align__(16) float d_x1[BT*400];        // layer0 output (tf32, natural)
__device__ __align__(16) float d_rnn[BT*400];       // layer1 output (fp32, natural)
__device__ __align__(16) float d_g[(size_t)BT*G16]; // gates: [bt][fwd 800 | bwd 800]
__device__ __align__(16) float d_h[2][2][2][Bsz*Hh];// [layer][dir][buf][b*200+u] packed
__device__ __align__(16) float d_hfin[2][Bsz*Hh];   // natural
__device__ __align__(16) float d_wcat[2][G16*400];  // padded tf32 W_ih, k pair-packed
__device__ __align__(16) float d_bcat[2][G16];
__device__ __align__(16) float d_mt[Tt*Bsz];        // keep-mask transposed [t][b]
__device__ unsigned d_barc[2][512];                 // per-layer: 16 groups x 32 counters

// ---------------- helpers ----------------
__device__ __forceinline__ float tanh_(float x) {
    float r;
    asm("tanh.approx.f32 %0, %1;" : "=f"(r) : "f"(x));
    return r;
}
__device__ __forceinline__ float sig_(float x) {
    return fmaf(tanh_(0.5f * x), 0.5f, 0.5f);
}
__device__ __forceinline__ float to_tf32(float x) {
    float r;
    asm("cvt.rna.tf32.f32 %0, %1;" : "=f"(r) : "f"(x));
    return r;
}
__device__ __forceinline__ void mma_tf32(float* d, const uint32_t* a, const uint32_t* b) {
    asm volatile(
        "mma.sync.aligned.m16n8k8.row.col.f32.tf32.tf32.f32 "
        "{%0,%1,%2,%3}, {%4,%5,%6,%7}, {%8,%9}, {%0,%1,%2,%3};"
        : "+f"(d[0]), "+f"(d[1]), "+f"(d[2]), "+f"(d[3])
        : "r"(a[0]), "r"(a[1]), "r"(a[2]), "r"(a[3]), "r"(b[0]), "r"(b[1]));
}
__device__ __forceinline__ void cp16(uint32_t saddr, const void* gaddr) {
    asm volatile("cp.async.cg.shared.global [%0], [%1], 16;" :: "r"(saddr), "l"(gaddr));
}
__device__ __forceinline__ unsigned ld_acq(const unsigned* p) {
    unsigned v;
    asm volatile("ld.acquire.gpu.global.u32 %0, [%1];" : "=r"(v) : "l"(p) : "memory");
    return v;
}
__device__ __forceinline__ void red_rel(unsigned* p) {
    asm volatile("red.release.gpu.global.add.u32 [%0], %1;" :: "l"(p), "r"(1u) : "memory");
}

// ---------------- fused embed + prep (also zeroes both layers' h + counters)
__global__ void embedprep_kernel(const int* __restrict__ words, const int* __restrict__ pos,
                                 const int* __restrict__ ner,
                                 const float* __restrict__ emb_w, const float* __restrict__ pos_w,
                                 const float* __restrict__ ner_w,
                                 const float* __restrict__ wf0, const float* __restrict__ wb0,
                                 const float* __restrict__ bf0, const float* __restrict__ bb0,
                                 const float* __restrict__ wf1, const float* __restrict__ wb1,
                                 const float* __restrict__ bf1, const float* __restrict__ bb1,
                                 const int* __restrict__ masks) {
    int i = blockIdx.x * blockDim.x + threadIdx.x;
    if (i < BT * 400) {
        int c = i % 400, bt = i / 400;
        float v = 0.f;
        if (c < 300)        v = emb_w[(size_t)words[bt] * 300 + c];
        else if (c < 330)   v = pos_w[(size_t)pos[bt] * 30 + (c - 300)];
        else if (c < 360)   v = ner_w[(size_t)ner[bt] * 30 + (c - 330)];
        d_x0[i] = to_tf32(v);
    }
    if (i < G16 * 400) {
        int n = i / 400, p = i % 400;
        int k0 = p >> 3, r = p & 7, tg = r >> 1, c = r & 1;
        int k = k0 * 8 + tg + 4 * c;
        int nn = (n < 800) ? n : n - 800;
        float v0 = 0.f, v1 = 0.f;
        if (k < 360) {
            const float* W = (n < 800) ? wf0 : wb0;
            v0 = to_tf32(W[(size_t)nn * 360 + k]);
        }
        {
            const float* W = (n < 800) ? wf1 : wb1;
            v1 = to_tf32(W[(size_t)nn * 400 + k]);
        }
        d_wcat[0][i] = v0;
        d_wcat[1][i] = v1;
    }
    if (i < G16) {
        d_bcat[0][i] = (i < 800) ? bf0[i] : bb0[i - 800];
        d_bcat[1][i] = (i < 800) ? bf1[i] : bb1[i - 800];
    }
    if (i < Tt * Bsz) {
        int t = i / Bsz, b = i % Bsz;
        d_mt[i] = (masks[b * Tt + t] == 0) ? 1.f : 0.f;
    }
    if (i < 2 * 2 * 2 * Bsz * Hh) ((float*)d_h)[i] = 0.f;
    if (i < 2 * 512) ((unsigned*)d_barc)[i] = 0;
}

// ---------------- TF32 GEMM: d_g[32768,1600] = A[32768,400] @ Wcat^T + bias -
// 256 threads, 8 warps (2x4), warp tile 64x40, BM=128, BN=160, BK=40,
// 2-stage cp.async double buffer, __launch_bounds__(256,2) -> 2 blocks/SM
// so one block's mma fills the other's wait/sync bubbles.
#define GSTG 12672   // floats per stage: A 128*44 + B 160*44

__global__ __launch_bounds__(256, 2)
void gemm_tf32(int asel, int layer) {
    extern __shared__ float smg[];
    const float* A = asel ? d_x1 : d_x0;
    const float* Wc = d_wcat[layer];
    const float* bc = d_bcat[layer];

    const int tid = threadIdx.x;
    const int lane = tid & 31, w = tid >> 5;
    const int wm = w & 1, wn = w >> 1;          // 2 x 4 warp grid
    const int g = lane >> 2, tg = lane & 3;
    const int m0 = blockIdx.y * 128, n0 = blockIdx.x * 160;

    const uint32_t sbase = (uint32_t)__cvta_generic_to_shared(smg);

    float acc[4][5][4];
#pragma unroll
    for (int i = 0; i < 4; i++)
#pragma unroll
        for (int j = 0; j < 5; j++)
#pragma unroll
            for (int r = 0; r < 4; r++) acc[i][j][r] = 0.f;

#define STAGE(IT, S) do {                                                      \
        int k0 = (IT) * 40;                                                    \
        uint32_t aB = sbase + (uint32_t)((S) * GSTG) * 4;                      \
        uint32_t bB = aB + 5632u * 4u;                                         \
        for (int i = tid; i < 1280; i += 256) {                                \
            int row = i / 10, c4 = (i % 10) * 4;                               \
            cp16(aB + (uint32_t)(row * 44 + c4) * 4,                           \
                 A + (size_t)(m0 + row) * 400 + k0 + c4);                      \
        }                                                                      \
        for (int i = tid; i < 1600; i += 256) {                                \
            int row = i / 10, c4 = (i % 10) * 4;                               \
            cp16(bB + (uint32_t)(row * 44 + c4) * 4,                           \
                 Wc + (size_t)(n0 + row) * 400 + k0 + c4);                     \
        }                                                                      \
        asm volatile("cp.async.commit_group;");                                \
    } while (0)

    STAGE(0, 0);

    for (int it = 0; it < 10; it++) {
        asm volatile("cp.async.wait_group 0;");
        __syncthreads();
        if (it + 1 < 10) STAGE(it + 1, (it + 1) & 1);

        const float* As = smg + (it & 1) * GSTG;
        const float* Bs = As + 5632;
#pragma unroll
        for (int ks = 0; ks < 5; ks++) {
            const int kb = ks * 8;
            uint32_t afr[4][4];
#pragma unroll
            for (int mi = 0; mi < 4; mi++) {
                int m = wm * 64 + mi * 16 + g;
                afr[mi][0] = __float_as_uint(As[m * 44 + kb + tg]);
                afr[mi][1] = __float_as_uint(As[(m + 8) * 44 + kb + tg]);
                afr[mi][2] = __float_as_uint(As[m * 44 + kb + tg + 4]);
                afr[mi][3] = __float_as_uint(As[(m + 8) * 44 + kb + tg + 4]);
            }
            uint32_t bfr[5][2];
#pragma unroll
            for (int nj = 0; nj < 5; nj++) {
                int n = wn * 40 + nj * 8 + g;
                float2 bp = *(const float2*)&Bs[n * 44 + kb + tg * 2];  // pair-packed
                bfr[nj][0] = __float_as_uint(bp.x);
                bfr[nj][1] = __float_as_uint(bp.y);
            }
#pragma unroll
            for (int mi = 0; mi < 4; mi++)
#pragma unroll
                for (int nj = 0; nj < 5; nj++)
                    mma_tf32(acc[mi][nj], afr[mi], bfr[nj]);
        }
    }
#undef STAGE

#pragma unroll
    for (int mi = 0; mi < 4; mi++) {
        int mrow = m0 + wm * 64 + mi * 16 + g;
#pragma unroll
        for (int nj = 0; nj < 5; nj++) {
            int ncol = n0 + wn * 40 + nj * 8 + 2 * tg;
            float bx = bc[ncol], by = bc[ncol + 1];
            *(float2*)(d_g + (size_t)mrow * G16 + ncol) =
                make_float2(acc[mi][nj][0] + bx, acc[mi][nj][1] + by);
            *(float2*)(d_g + (size_t)(mrow + 8) * G16 + ncol) =
                make_float2(acc[mi][nj][2] + bx, acc[mi][nj][3] + by);
        }
    }
}

// ---------------- persistent tensor-core bidirectional LSTM (R12 proven) ---
// 100 blocks = 2 dir x 2 batch-halves x 25 u-slices. 128 thr (4 warps).
// Sync: per-lane REDG counters. d_h k-pair-packed. MUFU activations.
#define NDB 25

__global__ __launch_bounds__(128, 1)
void lstm_layer(const float* __restrict__ Whhf, const float* __restrict__ Whhb, int layer) {
    extern __shared__ float sm[];
    float* hs = sm;            // [64][212] = 13568 floats
    float* Wp = sm + 13568;    // [32][206] = 6592 floats

    const int tid = threadIdx.x;
    const int lane = tid & 31, w = tid >> 5;   // w in 0..3
    const int bx = blockIdx.x;
    const int dir = bx / (2 * NDB);
    const int mh  = (bx / NDB) & 1;
    const int us  = bx % NDB;
    const int u0  = us * 8;
    const float* Whh = dir ? Whhb : Whhf;
    float* out = layer ? d_rnn : d_x1;
    float* hbuf0 = d_h[layer][dir][0];
    float* hbuf1 = d_h[layer][dir][1];

    // pack W_hh slice, tf32, pair-packed for float2 B-fragment loads
    for (int i = tid; i < 32 * 200; i += 128) {
        int n = i / 200, p = i % 200;
        int k0 = p >> 3, r = p & 7, tg2 = r >> 1, c = r & 1;
        int k = k0 * 8 + tg2 + 4 * c;
        int grow = (n >> 3) * Hh + u0 + (n & 7);
        Wp[n * 206 + p] = to_tf32(Whh[(size_t)grow * Hh + k]);
    }
    __syncthreads();

    const int m0 = mh * 64 + w * 16;   // global batch base for this warp
    const int lr0 = w * 16;            // local hs row base
    const int g = lane >> 2, tg = lane & 3;
    unsigned* bar = d_barc[layer] + (((dir * 2 + mh) * 4 + w) * 32);
    const uint32_t hs_base = (uint32_t)__cvta_generic_to_shared(hs);

    // packed positions (within 8-group) for this lane's two hidden units
    const int pu0 = (((2 * tg) & 3) << 1) | ((2 * tg) >> 2);          // u = u0+2tg
    const int pu1 = (((2 * tg + 1) & 3) << 1) | ((2 * tg + 1) >> 2);  // u = u0+2tg+1

    float cst[4] = {0.f, 0.f, 0.f, 0.f};
    float hreg[4] = {0.f, 0.f, 0.f, 0.f};

    // prefetch gates + mask for step 0
    float2 gx[4][2];
    float mk0, mk1;
    {
        int t0 = dir ? Tt - 1 : 0;
#pragma unroll
        for (int j = 0; j < 4; j++) {
            gx[j][0] = *(const float2*)&d_g[(size_t)((m0 + g) * Tt + t0) * G16 +
                                            dir * 800 + j * 200 + u0 + 2 * tg];
            gx[j][1] = *(const float2*)&d_g[(size_t)((m0 + g + 8) * Tt + t0) * G16 +
                                            dir * 800 + j * 200 + u0 + 2 * tg];
        }
        mk0 = d_mt[t0 * Bsz + m0 + g];
        mk1 = d_mt[t0 * Bsz + m0 + g + 8];
    }

    for (int s = 0; s < Tt; s++) {
        const int t = dir ? (Tt - 1 - s) : s;
        const float* hcur = (s & 1) ? hbuf1 : hbuf0;
        float* hnxt = (s & 1) ? hbuf0 : hbuf1;

        // wait for all 25 blocks of this warp-group to finish step s-1
        if (s) {
            unsigned tgt = (unsigned)NDB * (unsigned)s;
            while (ld_acq(&bar[lane]) < tgt) {}
        }
        __syncwarp();

        // bulk-stage this warp's 16 batch rows of h_prev (L1-bypassed)
        for (int i = lane; i < 800; i += 32) {
            int r16 = i / 50, c4 = (i % 50) * 4;
            cp16(hs_base + (uint32_t)((lr0 + r16) * 212 + c4) * 4,
                 hcur + (size_t)(m0 + r16) * Hh + c4);
        }
        asm volatile("cp.async.commit_group;");
        asm volatile("cp.async.wait_group 0;");
        __syncwarp();

        float acc[4][4];
#pragma unroll
        for (int j = 0; j < 4; j++)
#pragma unroll
            for (int r = 0; r < 4; r++) acc[j][r] = 0.f;

#pragma unroll
        for (int ik = 0; ik < 25; ik++) {
            const int kb = ik * 8;
            uint32_t a[4];
            {
                float2 f0 = *(const float2*)&hs[(lr0 + g) * 212 + kb + tg * 2];      // packed
                float2 f1 = *(const float2*)&hs[(lr0 + g + 8) * 212 + kb + tg * 2];
                a[0] = __float_as_uint(f0.x);
                a[1] = __float_as_uint(f1.x);
                a[2] = __float_as_uint(f0.y);
                a[3] = __float_as_uint(f1.y);
            }
#pragma unroll
            for (int j = 0; j < 4; j++) {
                float2 bp = *(const float2*)&Wp[(j * 8 + g) * 206 + kb + tg * 2];
                uint32_t bb[2] = { __float_as_uint(bp.x), __float_as_uint(bp.y) };
                mma_tf32(acc[j], a, bb);
            }
        }

#pragma unroll
        for (int j = 0; j < 4; j++) {
            acc[j][0] += gx[j][0].x; acc[j][1] += gx[j][0].y;
            acc[j][2] += gx[j][1].x; acc[j][3] += gx[j][1].y;
        }

        // cell update in registers (MUFU.TANH path)
        float ho[4];
#pragma unroll
        for (int r = 0; r < 4; r++) {
            float m = (r >> 1) ? mk1 : mk0;
            float iv = sig_(acc[0][r]);
            float fv = sig_(acc[1][r]);
            float gv = tanh_(acc[2][r]);
            float ov = sig_(acc[3][r]);
            float cn = fv * cst[r] + iv * gv;
            float hn = ov * tanh_(cn);
            float hnew = m * hn + (1.f - m) * hreg[r];
            cst[r] = m * cn + (1.f - m) * cst[r];
            hreg[r] = hnew;
            ho[r] = m * hn;
        }

        // store h_next (tf32, k-pair-packed positions)
        hnxt[(size_t)(m0 + g) * Hh + u0 + pu0]     = to_tf32(hreg[0]);
        hnxt[(size_t)(m0 + g) * Hh + u0 + pu1]     = to_tf32(hreg[1]);
        hnxt[(size_t)(m0 + g + 8) * Hh + u0 + pu0] = to_tf32(hreg[2]);
        hnxt[(size_t)(m0 + g + 8) * Hh + u0 + pu1] = to_tf32(hreg[3]);

        // release: each lane orders its own stores (spread-address REDG)
        red_rel(&bar[lane]);

        // ---- tail (off other blocks' critical path) ----
        {
            float2 o0 = make_float2(layer ? ho[0] : to_tf32(ho[0]),
                                    layer ? ho[1] : to_tf32(ho[1]));
            float2 o1 = make_float2(layer ? ho[2] : to_tf32(ho[2]),
                                    layer ? ho[3] : to_tf32(ho[3]));
            *(float2*)&out[(size_t)((m0 + g) * Tt + t) * IN1 + dir * Hh + u0 + 2 * tg] = o0;
            *(float2*)&out[(size_t)((m0 + g + 8) * Tt + t) * IN1 + dir * Hh + u0 + 2 * tg] = o1;
        }
        if (layer && s == Tt - 1) {
            *(float2*)&d_hfin[dir][(m0 + g) * Hh + u0 + 2 * tg] =
                make_float2(hreg[0], hreg[1]);
            *(float2*)&d_hfin[dir][(m0 + g + 8) * Hh + u0 + 2 * tg] =
                make_float2(hreg[2], hreg[3]);
        }
        if (s < Tt - 1) {
            int tn = dir ? (Tt - 2 - s) : (s + 1);
#pragma unroll
            for (int j = 0; j < 4; j++) {
                gx[j][0] = *(const float2*)&d_g[(size_t)((m0 + g) * Tt + tn) * G16 +
                                                dir * 800 + j * 200 + u0 + 2 * tg];
                gx[j][1] = *(const float2*)&d_g[(size_t)((m0 + g + 8) * Tt + tn) * G16 +
                                                dir * 800 + j * 200 + u0 + 2 * tg];
            }
            mk0 = d_mt[tn * Bsz + m0 + g];
            mk1 = d_mt[tn * Bsz + m0 + g + 8];
        }
    }
}

// ---------------- fused pool + MLP head: span sums + 3x attention + classify
__global__ __launch_bounds__(256)
void pool_final_kernel(const int* __restrict__ masks, const int* __restrict__ subj,
                       const int* __restrict__ obj,
                       const float* __restrict__ wo_w, const float* __restrict__ wo_b,
                       const float* __restrict__ ws_w, const float* __restrict__ ws_b,
                       const float* __restrict__ wg_w, const float* __restrict__ wg_b,
                       const float* __restrict__ cls_w, const float* __restrict__ cls_b,
                       float* __restrict__ outp) {
    int b = blockIdx.x;
    __shared__ float ssel[Tt];       // reused as hv[] for the head
    __shared__ float osel[Tt];
    __shared__ float qv[3][IN1];     // queries, then reused as attention outputs
    __shared__ float ps[3][Tt];
    __shared__ float red[256];
    int tid = threadIdx.x, lane = tid & 31, w = tid >> 5;

    for (int t = tid; t < Tt; t += 256) {
        int m = masks[b * Tt + t];
        ssel[t] = (subj[b * Tt + t] + m == 0) ? 1.f : 0.f;
        osel[t] = (obj[b * Tt + t] + m == 0) ? 1.f : 0.f;
    }
    __syncthreads();

    // pass 1: span sums -> queries (+ glob_h gather)
    for (int f = tid; f < IN1; f += 256) {
        float ss = 0.f, os = 0.f;
        for (int t = 0; t < Tt; t++) {
            float v = d_rnn[(size_t)(b * Tt + t) * IN1 + f];
            ss += v * ssel[t];
            os += v * osel[t];
        }
        qv[0][f] = os;
        qv[1][f] = ss;
        qv[2][f] = (f < Hh) ? d_hfin[1][b * Hh + f] : d_hfin[0][b * Hh + f - Hh];
    }
    __syncthreads();

    // pass 2: scoring (warp per t, 3 dots per row read)
    for (int t = w; t < Tt; t += 8) {
        const float* row = d_rnn + (size_t)(b * Tt + t) * IN1;
        float s0 = 0.f, s1 = 0.f, s2 = 0.f;
        for (int k = lane; k < IN1; k += 32) {
            float v = row[k];
            s0 += qv[0][k] * v;
            s1 += qv[1][k] * v;
            s2 += qv[2][k] * v;
        }
        for (int o = 16; o; o >>= 1) {
            s0 += __shfl_down_sync(0xffffffffu, s0, o);
            s1 += __shfl_down_sync(0xffffffffu, s1, o);
            s2 += __shfl_down_sync(0xffffffffu, s2, o);
        }
        if (lane == 0) {
            ps[0][t] = s0 * 0.05f;
            ps[1][t] = s1 * 0.05f;
            ps[2][t] = s2 * 0.05f;
        }
    }
    __syncthreads();

    {
        bool pad = masks[b * Tt + tid] != 0;
        if (pad) { ps[0][tid] = -1e9f; ps[1][tid] = -1e9f; ps[2][tid] = -1e9f; }
    }
    __syncthreads();

    // pass 3: softmax per query
#pragma unroll
    for (int qi = 0; qi < 3; qi++) {
        float sc = ps[qi][tid];
        red[tid] = sc; __syncthreads();
        for (int o = 128; o; o >>= 1) { if (tid < o) red[tid] = fmaxf(red[tid], red[tid + o]); __syncthreads(); }
        float mx = red[0]; __syncthreads();
        float e = __expf(sc - mx);
        red[tid] = e; __syncthreads();
        for (int o = 128; o; o >>= 1) { if (tid < o) red[tid] += red[tid + o]; __syncthreads(); }
        float inv = 1.f / red[0];
        __syncthreads();
        ps[qi][tid] = e * inv;
        __syncthreads();
    }

    // pass 4: weighted accumulation -> store into qv (queries no longer needed)
    float av[3][2];   // each thread handles up to 2 features (400/256 -> 2 strides)
#pragma unroll
    for (int r = 0; r < 2; r++) { av[0][r] = av[1][r] = av[2][r] = 0.f; }
    for (int t = 0; t < Tt; t++) {
        float p0 = ps[0][t], p1 = ps[1][t], p2 = ps[2][t];
        const float* row = d_rnn + (size_t)(b * Tt + t) * IN1;
#pragma unroll
        for (int r = 0; r < 2; r++) {
            int f = tid + 256 * r;
            if (f < IN1) {
                float v = row[f];
                av[0][r] += p0 * v;
                av[1][r] += p1 * v;
                av[2][r] += p2 * v;
            }
        }
    }
    __syncthreads();   // everyone done reading qv (pass 2 used it; already synced) — safe overwrite
#pragma unroll
    for (int r = 0; r < 2; r++) {
        int f = tid + 256 * r;
        if (f < IN1) {
            qv[0][f] = av[0][r];
            qv[1][f] = av[1][r];
            qv[2][f] = av[2][r];
        }
    }
    __syncthreads();

    // ---- MLP head: hv[j] = relu(att0@wo + att1@ws + att2@wg + biases) ----
    if (tid < Hh) {
        int j = tid;
        float a = wo_b[j] + ws_b[j] + wg_b[j];
        const float* wo = wo_w + (size_t)j * IN1;
        const float* ws = ws_w + (size_t)j * IN1;
        const float* wg = wg_w + (size_t)j * IN1;
        for (int k = 0; k < IN1; k++)
            a += qv[0][k] * wo[k] + qv[1][k] * ws[k] + qv[2][k] * wg[k];
        ssel[j] = fmaxf(a, 0.f);     // reuse ssel as hv
    }
    __syncthreads();
    if (tid < 64) {
        int n = tid >> 5, l = tid & 31;
        float p = 0.f;
        for (int k = l; k < Hh; k += 32) p += ssel[k] * cls_w[n * Hh + k];
        for (int o = 16; o; o >>= 1) p += __shfl_down_sync(0xffffffffu, p, o);
        if (l == 0) outp[b * NCLASS + n] = p + cls_b[n];
    }
}

// ---------------- launcher ----------------
extern "C" void kernel_launch(void* const* d_in, const int* in_sizes, int n_in,
                              void* d_out, int out_size) {
    const int*   words    = (const int*)d_in[0];
    const int*   masks    = (const int*)d_in[1];
    const int*   pos      = (const int*)d_in[2];
    const int*   ner      = (const int*)d_in[3];
    const int*   subj_pos = (const int*)d_in[4];
    const int*   obj_pos  = (const int*)d_in[5];
    const float* emb_w    = (const float*)d_in[6];
    const float* pos_w    = (const float*)d_in[7];
    const float* ner_w    = (const float*)d_in[8];
    const float* w_ih_l0f = (const float*)d_in[9];
    const float* w_hh_l0f = (const float*)d_in[10];
    const float* b_l0f    = (const float*)d_in[11];
    const float* w_ih_l0b = (const float*)d_in[12];
    const float* w_hh_l0b = (const float*)d_in[13];
    const float* b_l0b    = (const float*)d_in[14];
    const float* w_ih_l1f = (const float*)d_in[15];
    const float* w_hh_l1f = (const float*)d_in[16];
    const float* b_l1f    = (const float*)d_in[17];
    const float* w_ih_l1b = (const float*)d_in[18];
    const float* w_hh_l1b = (const float*)d_in[19];
    const float* b_l1b    = (const float*)d_in[20];
    const float* wo_w     = (const float*)d_in[21];
    const float* wo_b     = (const float*)d_in[22];
    const float* ws_w     = (const float*)d_in[23];
    const float* ws_b     = (const float*)d_in[24];
    const float* wg_w     = (const float*)d_in[25];
    const float* wg_b     = (const float*)d_in[26];
    const float* cls_w    = (const float*)d_in[27];
    const float* cls_b    = (const float*)d_in[28];

    static const int GEMM_SMEM = 2 * GSTG * 4;   // 101376 B (2 blocks/SM)
    static const int LSTM_SMEM = 20160 * 4;      // 80640 B
    cudaFuncSetAttribute(gemm_tf32, cudaFuncAttributeMaxDynamicSharedMemorySize, GEMM_SMEM);
    cudaFuncSetAttribute(lstm_layer, cudaFuncAttributeMaxDynamicSharedMemorySize, LSTM_SMEM);

    dim3 ggrid(10, 256);   // N=1600/160, M=32768/128

    embedprep_kernel<<<(BT * 400 + 255) / 256, 256>>>(
        words, pos, ner, emb_w, pos_w, ner_w,
        w_ih_l0f, w_ih_l0b, b_l0f, b_l0b,
        w_ih_l1f, w_ih_l1b, b_l1f, b_l1b, masks);                                        // 0
    gemm_tf32<<<ggrid, 256, GEMM_SMEM>>>(0, 0);                                           // 1
    lstm_layer<<<4 * NDB, 128, LSTM_SMEM>>>(w_hh_l0f, w_hh_l0b, 0);                       // 2
    gemm_tf32<<<ggrid, 256, GEMM_SMEM>>>(1, 1);                                           // 3
    lstm_layer<<<4 * NDB, 128, LSTM_SMEM>>>(w_hh_l1f, w_hh_l1b, 1);                       // 4
    pool_final_kernel<<<Bsz, 256>>>(masks, subj_pos, obj_pos,
                                    wo_w, wo_b, ws_w, ws_b, wg_w, wg_b, cls_w, cls_b,
                                    (float*)d_out);                                       // 5
}

// round 16
// speedup vs baseline: 1.2882x; 1.0056x over previous
#include <cuda_runtime.h>
#include <cstdint>

#define Bsz 128
#define Tt 256
#define Hh 200
#define IN1 400
#define BT (Bsz*Tt)
#define NCLASS 2
#define G16 1600

// ---------------- device scratch (static, no allocation) ----------------
__device__ __align__(16) float d_x0[BT*400];        // embeddings, tf32, natural layout
__device__ __align__(16) float d_x1[BT*400];        // layer0 output (tf32, natural)
__device__ __align__(16) float d_rnn[BT*400];       // layer1 output (fp32, natural)
__device__ __align__(16) float d_g[(size_t)BT*G16]; // gates: [bt][fwd 800 | bwd 800]
__device__ __align__(16) float d_h[2][2][2][Bsz*Hh];// [layer][dir][buf][b*200+u] packed
__device__ __align__(16) float d_hfin[2][Bsz*Hh];   // natural
__device__ __align__(16) float d_wcat[2][G16*400];  // padded tf32 W_ih, k pair-packed
__device__ __align__(16) float d_bcat[2][G16];
__device__ __align__(16) float d_mt[Tt*Bsz];        // keep-mask transposed [t][b]
__device__ unsigned d_barc[2][512];                 // per-layer: 16 groups x 32 counters

// ---------------- helpers ----------------
__device__ __forceinline__ float tanh_(float x) {
    float r;
    asm("tanh.approx.f32 %0, %1;" : "=f"(r) : "f"(x));
    return r;
}
__device__ __forceinline__ float sig_(float x) {
    return fmaf(tanh_(0.5f * x), 0.5f, 0.5f);
}
__device__ __forceinline__ float to_tf32(float x) {
    float r;
    asm("cvt.rna.tf32.f32 %0, %1;" : "=f"(r) : "f"(x));
    return r;
}
__device__ __forceinline__ void mma_tf32(float* d, const uint32_t* a, const uint32_t* b) {
    asm volatile(
        "mma.sync.aligned.m16n8k8.row.col.f32.tf32.tf32.f32 "
        "{%0,%1,%2,%3}, {%4,%5,%6,%7}, {%8,%9}, {%0,%1,%2,%3};"
        : "+f"(d[0]), "+f"(d[1]), "+f"(d[2]), "+f"(d[3])
        : "r"(a[0]), "r"(a[1]), "r"(a[2]), "r"(a[3]), "r"(b[0]), "r"(b[1]));
}
__device__ __forceinline__ void cp16(uint32_t saddr, const void* gaddr) {
    asm volatile("cp.async.cg.shared.global [%0], [%1], 16;" :: "r"(saddr), "l"(gaddr));
}
__device__ __forceinline__ unsigned ld_acq(const unsigned* p) {
    unsigned v;
    asm volatile("ld.acquire.gpu.global.u32 %0, [%1];" : "=r"(v) : "l"(p) : "memory");
    return v;
}
__device__ __forceinline__ void red_rel(unsigned* p) {
    asm volatile("red.release.gpu.global.add.u32 [%0], %1;" :: "l"(p), "r"(1u) : "memory");
}

// ---------------- fused embed + prep (also zeroes both layers' h + counters)
__global__ void embedprep_kernel(const int* __restrict__ words, const int* __restrict__ pos,
                                 const int* __restrict__ ner,
                                 const float* __restrict__ emb_w, const float* __restrict__ pos_w,
                                 const float* __restrict__ ner_w,
                                 const float* __restrict__ wf0, const float* __restrict__ wb0,
                                 const float* __restrict__ bf0, const float* __restrict__ bb0,
                                 const float* __restrict__ wf1, const float* __restrict__ wb1,
                                 const float* __restrict__ bf1, const float* __restrict__ bb1,
                                 const int* __restrict__ masks) {
    int i = blockIdx.x * blockDim.x + threadIdx.x;
    if (i < BT * 400) {
        int c = i % 400, bt = i / 400;
        if (c < 360) {   // cols 360..399 never read (gemm0 runs 9 K-iters)
            float v;
            if (c < 300)        v = emb_w[(size_t)words[bt] * 300 + c];
            else if (c < 330)   v = pos_w[(size_t)pos[bt] * 30 + (c - 300)];
            else                v = ner_w[(size_t)ner[bt] * 30 + (c - 330)];
            d_x0[i] = to_tf32(v);
        }
    }
    if (i < G16 * 400) {
        int n = i / 400, p = i % 400;
        int k0 = p >> 3, r = p & 7, tg = r >> 1, c = r & 1;
        int k = k0 * 8 + tg + 4 * c;
        int nn = (n < 800) ? n : n - 800;
        if (k < 360) {
            const float* W = (n < 800) ? wf0 : wb0;
            d_wcat[0][i] = to_tf32(W[(size_t)nn * 360 + k]);
        }
        {
            const float* W = (n < 800) ? wf1 : wb1;
            d_wcat[1][i] = to_tf32(W[(size_t)nn * 400 + k]);
        }
    }
    if (i < G16) {
        d_bcat[0][i] = (i < 800) ? bf0[i] : bb0[i - 800];
        d_bcat[1][i] = (i < 800) ? bf1[i] : bb1[i - 800];
    }
    if (i < Tt * Bsz) {
        int t = i / Bsz, b = i % Bsz;
        d_mt[i] = (masks[b * Tt + t] == 0) ? 1.f : 0.f;
    }
    if (i < 2 * 2 * 2 * Bsz * Hh) ((float*)d_h)[i] = 0.f;
    if (i < 2 * 512) ((unsigned*)d_barc)[i] = 0;
}

// ---------------- TF32 GEMM: d_g[32768,1600] = A[32768,K] @ Wcat^T + bias ---
// 256 threads, 8 warps (2x4), warp tile 64x40, BM=128, BN=160, BK=40,
// 2-stage cp.async double buffer, 2 blocks/SM. niter = K/40 (9 for layer 0).
#define GSTG 12672   // floats per stage: A 128*44 + B 160*44

__global__ __launch_bounds__(256, 2)
void gemm_tf32(int asel, int layer, int niter) {
    extern __shared__ float smg[];
    const float* A = asel ? d_x1 : d_x0;
    const float* Wc = d_wcat[layer];
    const float* bc = d_bcat[layer];

    const int tid = threadIdx.x;
    const int lane = tid & 31, w = tid >> 5;
    const int wm = w & 1, wn = w >> 1;          // 2 x 4 warp grid
    const int g = lane >> 2, tg = lane & 3;
    const int m0 = blockIdx.y * 128, n0 = blockIdx.x * 160;

    const uint32_t sbase = (uint32_t)__cvta_generic_to_shared(smg);

    float acc[4][5][4];
#pragma unroll
    for (int i = 0; i < 4; i++)
#pragma unroll
        for (int j = 0; j < 5; j++)
#pragma unroll
            for (int r = 0; r < 4; r++) acc[i][j][r] = 0.f;

#define STAGE(IT, S) do {                                                      \
        int k0 = (IT) * 40;                                                    \
        uint32_t aB = sbase + (uint32_t)((S) * GSTG) * 4;                      \
        uint32_t bB = aB + 5632u * 4u;                                         \
        for (int i = tid; i < 1280; i += 256) {                                \
            int row = i / 10, c4 = (i % 10) * 4;                               \
            cp16(aB + (uint32_t)(row * 44 + c4) * 4,                           \
                 A + (size_t)(m0 + row) * 400 + k0 + c4);                      \
        }                                                                      \
        for (int i = tid; i < 1600; i += 256) {                                \
            int row = i / 10, c4 = (i % 10) * 4;                               \
            cp16(bB + (uint32_t)(row * 44 + c4) * 4,                           \
                 Wc + (size_t)(n0 + row) * 400 + k0 + c4);                     \
        }                                                                      \
        asm volatile("cp.async.commit_group;");                                \
    } while (0)

    STAGE(0, 0);

    for (int it = 0; it < niter; it++) {
        asm volatile("cp.async.wait_group 0;");
        __syncthreads();
        if (it + 1 < niter) STAGE(it + 1, (it + 1) & 1);

        const float* As = smg + (it & 1) * GSTG;
        const float* Bs = As + 5632;
#pragma unroll
        for (int ks = 0; ks < 5; ks++) {
            const int kb = ks * 8;
            uint32_t afr[4][4];
#pragma unroll
            for (int mi = 0; mi < 4; mi++) {
                int m = wm * 64 + mi * 16 + g;
                afr[mi][0] = __float_as_uint(As[m * 44 + kb + tg]);
                afr[mi][1] = __float_as_uint(As[(m + 8) * 44 + kb + tg]);
                afr[mi][2] = __float_as_uint(As[m * 44 + kb + tg + 4]);
                afr[mi][3] = __float_as_uint(As[(m + 8) * 44 + kb + tg + 4]);
            }
            uint32_t bfr[5][2];
#pragma unroll
            for (int nj = 0; nj < 5; nj++) {
                int n = wn * 40 + nj * 8 + g;
                float2 bp = *(const float2*)&Bs[n * 44 + kb + tg * 2];  // pair-packed
                bfr[nj][0] = __float_as_uint(bp.x);
                bfr[nj][1] = __float_as_uint(bp.y);
            }
#pragma unroll
            for (int mi = 0; mi < 4; mi++)
#pragma unroll
                for (int nj = 0; nj < 5; nj++)
                    mma_tf32(acc[mi][nj], afr[mi], bfr[nj]);
        }
    }
#undef STAGE

#pragma unroll
    for (int mi = 0; mi < 4; mi++) {
        int mrow = m0 + wm * 64 + mi * 16 + g;
#pragma unroll
        for (int nj = 0; nj < 5; nj++) {
            int ncol = n0 + wn * 40 + nj * 8 + 2 * tg;
            float bx = bc[ncol], by = bc[ncol + 1];
            *(float2*)(d_g + (size_t)mrow * G16 + ncol) =
                make_float2(acc[mi][nj][0] + bx, acc[mi][nj][1] + by);
            *(float2*)(d_g + (size_t)(mrow + 8) * G16 + ncol) =
                make_float2(acc[mi][nj][2] + bx, acc[mi][nj][3] + by);
        }
    }
}

// ---------------- persistent tensor-core bidirectional LSTM (R12 proven) ---
// 100 blocks = 2 dir x 2 batch-halves x 25 u-slices. 128 thr (4 warps).
// Sync: per-lane REDG counters. d_h k-pair-packed. MUFU activations.
#define NDB 25

__global__ __launch_bounds__(128, 1)
void lstm_layer(const float* __restrict__ Whhf, const float* __restrict__ Whhb, int layer) {
    extern __shared__ float sm[];
    float* hs = sm;            // [64][212] = 13568 floats
    float* Wp = sm + 13568;    // [32][206] = 6592 floats

    const int tid = threadIdx.x;
    const int lane = tid & 31, w = tid >> 5;   // w in 0..3
    const int bx = blockIdx.x;
    const int dir = bx / (2 * NDB);
    const int mh  = (bx / NDB) & 1;
    const int us  = bx % NDB;
    const int u0  = us * 8;
    const float* Whh = dir ? Whhb : Whhf;
    float* out = layer ? d_rnn : d_x1;
    float* hbuf0 = d_h[layer][dir][0];
    float* hbuf1 = d_h[layer][dir][1];

    // pack W_hh slice, tf32, pair-packed for float2 B-fragment loads
    for (int i = tid; i < 32 * 200; i += 128) {
        int n = i / 200, p = i % 200;
        int k0 = p >> 3, r = p & 7, tg2 = r >> 1, c = r & 1;
        int k = k0 * 8 + tg2 + 4 * c;
        int grow = (n >> 3) * Hh + u0 + (n & 7);
        Wp[n * 206 + p] = to_tf32(Whh[(size_t)grow * Hh + k]);
    }
    __syncthreads();

    const int m0 = mh * 64 + w * 16;   // global batch base for this warp
    const int lr0 = w * 16;            // local hs row base
    const int g = lane >> 2, tg = lane & 3;
    unsigned* bar = d_barc[layer] + (((dir * 2 + mh) * 4 + w) * 32);
    const uint32_t hs_base = (uint32_t)__cvta_generic_to_shared(hs);

    // packed positions (within 8-group) for this lane's two hidden units
    const int pu0 = (((2 * tg) & 3) << 1) | ((2 * tg) >> 2);          // u = u0+2tg
    const int pu1 = (((2 * tg + 1) & 3) << 1) | ((2 * tg + 1) >> 2);  // u = u0+2tg+1

    float cst[4] = {0.f, 0.f, 0.f, 0.f};
    float hreg[4] = {0.f, 0.f, 0.f, 0.f};

    // prefetch gates + mask for step 0
    float2 gx[4][2];
    float mk0, mk1;
    {
        int t0 = dir ? Tt - 1 : 0;
#pragma unroll
        for (int j = 0; j < 4; j++) {
            gx[j][0] = *(const float2*)&d_g[(size_t)((m0 + g) * Tt + t0) * G16 +
                                            dir * 800 + j * 200 + u0 + 2 * tg];
            gx[j][1] = *(const float2*)&d_g[(size_t)((m0 + g + 8) * Tt + t0) * G16 +
                                            dir * 800 + j * 200 + u0 + 2 * tg];
        }
        mk0 = d_mt[t0 * Bsz + m0 + g];
        mk1 = d_mt[t0 * Bsz + m0 + g + 8];
    }

    for (int s = 0; s < Tt; s++) {
        const int t = dir ? (Tt - 1 - s) : s;
        const float* hcur = (s & 1) ? hbuf1 : hbuf0;
        float* hnxt = (s & 1) ? hbuf0 : hbuf1;

        // wait for all 25 blocks of this warp-group to finish step s-1
        if (s) {
            unsigned tgt = (unsigned)NDB * (unsigned)s;
            while (ld_acq(&bar[lane]) < tgt) {}
        }
        __syncwarp();

        // bulk-stage this warp's 16 batch rows of h_prev (L1-bypassed)
        for (int i = lane; i < 800; i += 32) {
            int r16 = i / 50, c4 = (i % 50) * 4;
            cp16(hs_base + (uint32_t)((lr0 + r16) * 212 + c4) * 4,
                 hcur + (size_t)(m0 + r16) * Hh + c4);
        }
        asm volatile("cp.async.commit_group;");
        asm volatile("cp.async.wait_group 0;");
        __syncwarp();

        float acc[4][4];
#pragma unroll
        for (int j = 0; j < 4; j++)
#pragma unroll
            for (int r = 0; r < 4; r++) acc[j][r] = 0.f;

#pragma unroll
        for (int ik = 0; ik < 25; ik++) {
            const int kb = ik * 8;
            uint32_t a[4];
            {
                float2 f0 = *(const float2*)&hs[(lr0 + g) * 212 + kb + tg * 2];      // packed
                float2 f1 = *(const float2*)&hs[(lr0 + g + 8) * 212 + kb + tg * 2];
                a[0] = __float_as_uint(f0.x);
                a[1] = __float_as_uint(f1.x);
                a[2] = __float_as_uint(f0.y);
                a[3] = __float_as_uint(f1.y);
            }
#pragma unroll
            for (int j = 0; j < 4; j++) {
                float2 bp = *(const float2*)&Wp[(j * 8 + g) * 206 + kb + tg * 2];
                uint32_t bb[2] = { __float_as_uint(bp.x), __float_as_uint(bp.y) };
                mma_tf32(acc[j], a, bb);
            }
        }

#pragma unroll
        for (int j = 0; j < 4; j++) {
            acc[j][0] += gx[j][0].x; acc[j][1] += gx[j][0].y;
            acc[j][2] += gx[j][1].x; acc[j][3] += gx[j][1].y;
        }

        // cell update in registers (MUFU.TANH path)
        float ho[4];
#pragma unroll
        for (int r = 0; r < 4; r++) {
            float m = (r >> 1) ? mk1 : mk0;
            float iv = sig_(acc[0][r]);
            float fv = sig_(acc[1][r]);
            float gv = tanh_(acc[2][r]);
            float ov = sig_(acc[3][r]);
            float cn = fv * cst[r] + iv * gv;
            float hn = ov * tanh_(cn);
            float hnew = m * hn + (1.f - m) * hreg[r];
            cst[r] = m * cn + (1.f - m) * cst[r];
            hreg[r] = hnew;
            ho[r] = m * hn;
        }

        // store h_next (tf32, k-pair-packed positions)
        hnxt[(size_t)(m0 + g) * Hh + u0 + pu0]     = to_tf32(hreg[0]);
        hnxt[(size_t)(m0 + g) * Hh + u0 + pu1]     = to_tf32(hreg[1]);
        hnxt[(size_t)(m0 + g + 8) * Hh + u0 + pu0] = to_tf32(hreg[2]);
        hnxt[(size_t)(m0 + g + 8) * Hh + u0 + pu1] = to_tf32(hreg[3]);

        // release: each lane orders its own stores (spread-address REDG)
        red_rel(&bar[lane]);

        // ---- tail (off other blocks' critical path) ----
        {
            float2 o0 = make_float2(layer ? ho[0] : to_tf32(ho[0]),
                                    layer ? ho[1] : to_tf32(ho[1]));
            float2 o1 = make_float2(layer ? ho[2] : to_tf32(ho[2]),
                                    layer ? ho[3] : to_tf32(ho[3]));
            *(float2*)&out[(size_t)((m0 + g) * Tt + t) * IN1 + dir * Hh + u0 + 2 * tg] = o0;
            *(float2*)&out[(size_t)((m0 + g + 8) * Tt + t) * IN1 + dir * Hh + u0 + 2 * tg] = o1;
        }
        if (layer && s == Tt - 1) {
            *(float2*)&d_hfin[dir][(m0 + g) * Hh + u0 + 2 * tg] =
                make_float2(hreg[0], hreg[1]);
            *(float2*)&d_hfin[dir][(m0 + g + 8) * Hh + u0 + 2 * tg] =
                make_float2(hreg[2], hreg[3]);
        }
        if (s < Tt - 1) {
            int tn = dir ? (Tt - 2 - s) : (s + 1);
#pragma unroll
            for (int j = 0; j < 4; j++) {
                gx[j][0] = *(const float2*)&d_g[(size_t)((m0 + g) * Tt + tn) * G16 +
                                                dir * 800 + j * 200 + u0 + 2 * tg];
                gx[j][1] = *(const float2*)&d_g[(size_t)((m0 + g + 8) * Tt + tn) * G16 +
                                                dir * 800 + j * 200 + u0 + 2 * tg];
            }
            mk0 = d_mt[tn * Bsz + m0 + g];
            mk1 = d_mt[tn * Bsz + m0 + g + 8];
        }
    }
}

// ---------------- fused pool + MLP head: span sums + 3x attention + classify
__global__ __launch_bounds__(256)
void pool_final_kernel(const int* __restrict__ masks, const int* __restrict__ subj,
                       const int* __restrict__ obj,
                       const float* __restrict__ wo_w, const float* __restrict__ wo_b,
                       const float* __restrict__ ws_w, const float* __restrict__ ws_b,
                       const float* __restrict__ wg_w, const float* __restrict__ wg_b,
                       const float* __restrict__ cls_w, const float* __restrict__ cls_b,
                       float* __restrict__ outp) {
    int b = blockIdx.x;
    __shared__ float ssel[Tt];       // reused as hv[] for the head
    __shared__ float osel[Tt];
    __shared__ float qv[3][IN1];     // queries, then reused as attention outputs
    __shared__ float ps[3][Tt];
    __shared__ float red[256];
    int tid = threadIdx.x, lane = tid & 31, w = tid >> 5;

    for (int t = tid; t < Tt; t += 256) {
        int m = masks[b * Tt + t];
        ssel[t] = (subj[b * Tt + t] + m == 0) ? 1.f : 0.f;
        osel[t] = (obj[b * Tt + t] + m == 0) ? 1.f : 0.f;
    }
    __syncthreads();

    // pass 1: span sums -> queries (+ glob_h gather)
    for (int f = tid; f < IN1; f += 256) {
        float ss = 0.f, os = 0.f;
        for (int t = 0; t < Tt; t++) {
            float v = d_rnn[(size_t)(b * Tt + t) * IN1 + f];
            ss += v * ssel[t];
            os += v * osel[t];
        }
        qv[0][f] = os;
        qv[1][f] = ss;
        qv[2][f] = (f < Hh) ? d_hfin[1][b * Hh + f] : d_hfin[0][b * Hh + f - Hh];
    }
    __syncthreads();

    // pass 2: scoring (warp per t, 3 dots per row read)
    for (int t = w; t < Tt; t += 8) {
        const float* row = d_rnn + (size_t)(b * Tt + t) * IN1;
        float s0 = 0.f, s1 = 0.f, s2 = 0.f;
        for (int k = lane; k < IN1; k += 32) {
            float v = row[k];
            s0 += qv[0][k] * v;
            s1 += qv[1][k] * v;
            s2 += qv[2][k] * v;
        }
        for (int o = 16; o; o >>= 1) {
            s0 += __shfl_down_sync(0xffffffffu, s0, o);
            s1 += __shfl_down_sync(0xffffffffu, s1, o);
            s2 += __shfl_down_sync(0xffffffffu, s2, o);
        }
        if (lane == 0) {
            ps[0][t] = s0 * 0.05f;
            ps[1][t] = s1 * 0.05f;
            ps[2][t] = s2 * 0.05f;
        }
    }
    __syncthreads();

    {
        bool pad = masks[b * Tt + tid] != 0;
        if (pad) { ps[0][tid] = -1e9f; ps[1][tid] = -1e9f; ps[2][tid] = -1e9f; }
    }
    __syncthreads();

    // pass 3: softmax per query
#pragma unroll
    for (int qi = 0; qi < 3; qi++) {
        float sc = ps[qi][tid];
        red[tid] = sc; __syncthreads();
        for (int o = 128; o; o >>= 1) { if (tid < o) red[tid] = fmaxf(red[tid], red[tid + o]); __syncthreads(); }
        float mx = red[0]; __syncthreads();
        float e = __expf(sc - mx);
        red[tid] = e; __syncthreads();
        for (int o = 128; o; o >>= 1) { if (tid < o) red[tid] += red[tid + o]; __syncthreads(); }
        float inv = 1.f / red[0];
        __syncthreads();
        ps[qi][tid] = e * inv;
        __syncthreads();
    }

    // pass 4: weighted accumulation -> store into qv (queries no longer needed)
    float av[3][2];
#pragma unroll
    for (int r = 0; r < 2; r++) { av[0][r] = av[1][r] = av[2][r] = 0.f; }
    for (int t = 0; t < Tt; t++) {
        float p0 = ps[0][t], p1 = ps[1][t], p2 = ps[2][t];
        const float* row = d_rnn + (size_t)(b * Tt + t) * IN1;
#pragma unroll
        for (int r = 0; r < 2; r++) {
            int f = tid + 256 * r;
            if (f < IN1) {
                float v = row[f];
                av[0][r] += p0 * v;
                av[1][r] += p1 * v;
                av[2][r] += p2 * v;
            }
        }
    }
    __syncthreads();
#pragma unroll
    for (int r = 0; r < 2; r++) {
        int f = tid + 256 * r;
        if (f < IN1) {
            qv[0][f] = av[0][r];
            qv[1][f] = av[1][r];
            qv[2][f] = av[2][r];
        }
    }
    __syncthreads();

    // ---- MLP head ----
    if (tid < Hh) {
        int j = tid;
        float a = wo_b[j] + ws_b[j] + wg_b[j];
        const float* wo = wo_w + (size_t)j * IN1;
        const float* ws = ws_w + (size_t)j * IN1;
        const float* wg = wg_w + (size_t)j * IN1;
        for (int k = 0; k < IN1; k++)
            a += qv[0][k] * wo[k] + qv[1][k] * ws[k] + qv[2][k] * wg[k];
        ssel[j] = fmaxf(a, 0.f);
    }
    __syncthreads();
    if (tid < 64) {
        int n = tid >> 5, l = tid & 31;
        float p = 0.f;
        for (int k = l; k < Hh; k += 32) p += ssel[k] * cls_w[n * Hh + k];
        for (int o = 16; o; o >>= 1) p += __shfl_down_sync(0xffffffffu, p, o);
        if (l == 0) outp[b * NCLASS + n] = p + cls_b[n];
    }
}

// ---------------- launcher ----------------
extern "C" void kernel_launch(void* const* d_in, const int* in_sizes, int n_in,
                              void* d_out, int out_size) {
    const int*   words    = (const int*)d_in[0];
    const int*   masks    = (const int*)d_in[1];
    const int*   pos      = (const int*)d_in[2];
    const int*   ner      = (const int*)d_in[3];
    const int*   subj_pos = (const int*)d_in[4];
    const int*   obj_pos  = (const int*)d_in[5];
    const float* emb_w    = (const float*)d_in[6];
    const float* pos_w    = (const float*)d_in[7];
    const float* ner_w    = (const float*)d_in[8];
    const float* w_ih_l0f = (const float*)d_in[9];
    const float* w_hh_l0f = (const float*)d_in[10];
    const float* b_l0f    = (const float*)d_in[11];
    const float* w_ih_l0b = (const float*)d_in[12];
    const float* w_hh_l0b = (const float*)d_in[13];
    const float* b_l0b    = (const float*)d_in[14];
    const float* w_ih_l1f = (const float*)d_in[15];
    const float* w_hh_l1f = (const float*)d_in[16];
    const float* b_l1f    = (const float*)d_in[17];
    const float* w_ih_l1b = (const float*)d_in[18];
    const float* w_hh_l1b = (const float*)d_in[19];
    const float* b_l1b    = (const float*)d_in[20];
    const float* wo_w     = (const float*)d_in[21];
    const float* wo_b     = (const float*)d_in[22];
    const float* ws_w     = (const float*)d_in[23];
    const float* ws_b     = (const float*)d_in[24];
    const float* wg_w     = (const float*)d_in[25];
    const float* wg_b     = (const float*)d_in[26];
    const float* cls_w    = (const float*)d_in[27];
    const float* cls_b    = (const float*)d_in[28];

    static const int GEMM_SMEM = 2 * GSTG * 4;   // 101376 B (2 blocks/SM)
    static const int LSTM_SMEM = 20160 * 4;      // 80640 B
    cudaFuncSetAttribute(gemm_tf32, cudaFuncAttributeMaxDynamicSharedMemorySize, GEMM_SMEM);
    cudaFuncSetAttribute(lstm_layer, cudaFuncAttributeMaxDynamicSharedMemorySize, LSTM_SMEM);

    dim3 ggrid(10, 256);   // N=1600/160, M=32768/128

    embedprep_kernel<<<(BT * 400 + 255) / 256, 256>>>(
        words, pos, ner, emb_w, pos_w, ner_w,
        w_ih_l0f, w_ih_l0b, b_l0f, b_l0b,
        w_ih_l1f, w_ih_l1b, b_l1f, b_l1b, masks);                                        // 0
    gemm_tf32<<<ggrid, 256, GEMM_SMEM>>>(0, 0, 9);    // K=360                            // 1
    lstm_layer<<<4 * NDB, 128, LSTM_SMEM>>>(w_hh_l0f, w_hh_l0b, 0);                       // 2
    gemm_tf32<<<ggrid, 256, GEMM_SMEM>>>(1, 1, 10);   // K=400                            // 3
    lstm_layer<<<4 * NDB, 128, LSTM_SMEM>>>(w_hh_l1f, w_hh_l1b, 1);                       // 4
    pool_final_kernel<<<Bsz, 256>>>(masks, subj_pos, obj_pos,
                                    wo_w, wo_b, ws_w, ws_b, wg_w, wg_b, cls_w, cls_b,
                                    (float*)d_out);                                       // 5
}

// round 17
// speedup vs baseline: 1.2935x; 1.0041x over previous
#include <cuda_runtime.h>
#include <cstdint>

#define Bsz 128
#define Tt 256
#define Hh 200
#define IN1 400
#define BT (Bsz*Tt)
#define NCLASS 2
#define G16 1600

// ---------------- device scratch (static, no allocation) ----------------
__device__ __align__(16) float d_x0[BT*400];        // embeddings, tf32, natural layout
__device__ __align__(16) float d_x1[BT*400];        // layer0 output (tf32, natural)
__device__ __align__(16) float d_rnn[BT*400];       // layer1 output (fp32, natural)
__device__ __align__(16) float d_g[(size_t)BT*G16]; // gates: [bt][fwd 800 | bwd 800]
__device__ __align__(16) float d_h[2][2][2][Bsz*Hh];// [layer][dir][buf][b*200+u] packed
__device__ __align__(16) float d_hfin[2][Bsz*Hh];   // natural
__device__ __align__(16) float d_wcat[2][G16*400];  // padded tf32 W_ih, k pair-packed
__device__ __align__(16) float d_bcat[2][G16];
__device__ __align__(16) float d_mt[Tt*Bsz];        // keep-mask transposed [t][b]
__device__ unsigned d_barc[2][512];                 // per-layer: 16 groups x 32 counters

// ---------------- helpers ----------------
__device__ __forceinline__ float tanh_(float x) {
    float r;
    asm("tanh.approx.f32 %0, %1;" : "=f"(r) : "f"(x));
    return r;
}
__device__ __forceinline__ float sig_(float x) {
    return fmaf(tanh_(0.5f * x), 0.5f, 0.5f);
}
__device__ __forceinline__ float to_tf32(float x) {
    float r;
    asm("cvt.rna.tf32.f32 %0, %1;" : "=f"(r) : "f"(x));
    return r;
}
__device__ __forceinline__ void mma_tf32(float* d, const uint32_t* a, const uint32_t* b) {
    asm volatile(
        "mma.sync.aligned.m16n8k8.row.col.f32.tf32.tf32.f32 "
        "{%0,%1,%2,%3}, {%4,%5,%6,%7}, {%8,%9}, {%0,%1,%2,%3};"
        : "+f"(d[0]), "+f"(d[1]), "+f"(d[2]), "+f"(d[3])
        : "r"(a[0]), "r"(a[1]), "r"(a[2]), "r"(a[3]), "r"(b[0]), "r"(b[1]));
}
__device__ __forceinline__ void cp16(uint32_t saddr, const void* gaddr) {
    asm volatile("cp.async.cg.shared.global [%0], [%1], 16;" :: "r"(saddr), "l"(gaddr));
}
__device__ __forceinline__ unsigned ld_acq(const unsigned* p) {
    unsigned v;
    asm volatile("ld.acquire.gpu.global.u32 %0, [%1];" : "=r"(v) : "l"(p) : "memory");
    return v;
}
__device__ __forceinline__ void red_rel(unsigned* p) {
    asm volatile("red.release.gpu.global.add.u32 [%0], %1;" :: "l"(p), "r"(1u) : "memory");
}

// ---------------- fused embed + prep (also zeroes both layers' h + counters)
__global__ void embedprep_kernel(const int* __restrict__ words, const int* __restrict__ pos,
                                 const int* __restrict__ ner,
                                 const float* __restrict__ emb_w, const float* __restrict__ pos_w,
                                 const float* __restrict__ ner_w,
                                 const float* __restrict__ wf0, const float* __restrict__ wb0,
                                 const float* __restrict__ bf0, const float* __restrict__ bb0,
                                 const float* __restrict__ wf1, const float* __restrict__ wb1,
                                 const float* __restrict__ bf1, const float* __restrict__ bb1,
                                 const int* __restrict__ masks) {
    int i = blockIdx.x * blockDim.x + threadIdx.x;
    if (i < BT * 400) {
        int c = i % 400, bt = i / 400;
        if (c < 360) {   // cols 360..399 never read (gemm0 runs 9 K-iters)
            float v;
            if (c < 300)        v = emb_w[(size_t)words[bt] * 300 + c];
            else if (c < 330)   v = pos_w[(size_t)pos[bt] * 30 + (c - 300)];
            else                v = ner_w[(size_t)ner[bt] * 30 + (c - 330)];
            d_x0[i] = to_tf32(v);
        }
    }
    if (i < G16 * 400) {
        int n = i / 400, p = i % 400;
        int k0 = p >> 3, r = p & 7, tg = r >> 1, c = r & 1;
        int k = k0 * 8 + tg + 4 * c;
        int nn = (n < 800) ? n : n - 800;
        if (k < 360) {
            const float* W = (n < 800) ? wf0 : wb0;
            d_wcat[0][i] = to_tf32(W[(size_t)nn * 360 + k]);
        }
        {
            const float* W = (n < 800) ? wf1 : wb1;
            d_wcat[1][i] = to_tf32(W[(size_t)nn * 400 + k]);
        }
    }
    if (i < G16) {
        d_bcat[0][i] = (i < 800) ? bf0[i] : bb0[i - 800];
        d_bcat[1][i] = (i < 800) ? bf1[i] : bb1[i - 800];
    }
    if (i < Tt * Bsz) {
        int t = i / Bsz, b = i % Bsz;
        d_mt[i] = (masks[b * Tt + t] == 0) ? 1.f : 0.f;
    }
    if (i < 2 * 2 * 2 * Bsz * Hh) ((float*)d_h)[i] = 0.f;
    if (i < 2 * 512) ((unsigned*)d_barc)[i] = 0;
}

// ---------------- TF32 GEMM: d_g[32768,1600] = A[32768,K] @ Wcat^T + bias ---
// 256 threads, 8 warps (2x4), warp tile 64x40, BM=128, BN=160, BK=40,
// 2-stage cp.async double buffer, 2 blocks/SM. Stage addressing hoisted
// out of the mainloop (loop-invariant except +k0 and buffer select).
#define GSTG 12672   // floats per stage: A 128*44 + B 160*44

__global__ __launch_bounds__(256, 2)
void gemm_tf32(int asel, int layer, int niter) {
    extern __shared__ float smg[];
    const float* A = asel ? d_x1 : d_x0;
    const float* Wc = d_wcat[layer];
    const float* bc = d_bcat[layer];

    const int tid = threadIdx.x;
    const int lane = tid & 31, w = tid >> 5;
    const int wm = w & 1, wn = w >> 1;          // 2 x 4 warp grid
    const int g = lane >> 2, tg = lane & 3;
    const int m0 = blockIdx.y * 128, n0 = blockIdx.x * 160;

    const uint32_t sbase = (uint32_t)__cvta_generic_to_shared(smg);

    // hoisted stage addressing: 5 A copies + up to 7 B copies per thread
    uint32_t aS[5];  const float* aG[5];
    uint32_t bS[7];  const float* bG[7];
#pragma unroll
    for (int j = 0; j < 5; j++) {
        int i = tid + 256 * j;
        int row = i / 10, c4 = (i % 10) * 4;
        aS[j] = (uint32_t)(row * 44 + c4) * 4;
        aG[j] = A + (size_t)(m0 + row) * 400 + c4;
    }
#pragma unroll
    for (int j = 0; j < 7; j++) {
        int i = tid + 256 * j;
        if (i < 1600) {
            int row = i / 10, c4 = (i % 10) * 4;
            bS[j] = (uint32_t)(row * 44 + c4) * 4;
            bG[j] = Wc + (size_t)(n0 + row) * 400 + c4;
        } else { bS[j] = 0; bG[j] = nullptr; }
    }

    float acc[4][5][4];
#pragma unroll
    for (int i = 0; i < 4; i++)
#pragma unroll
        for (int j = 0; j < 5; j++)
#pragma unroll
            for (int r = 0; r < 4; r++) acc[i][j][r] = 0.f;

#define STAGE(K0, S) do {                                                      \
        uint32_t aB = sbase + (uint32_t)((S) * GSTG) * 4;                      \
        uint32_t bB = aB + 5632u * 4u;                                         \
        _Pragma("unroll")                                                      \
        for (int j = 0; j < 5; j++) cp16(aB + aS[j], aG[j] + (K0));            \
        _Pragma("unroll")                                                      \
        for (int j = 0; j < 7; j++)                                            \
            if (bG[j]) cp16(bB + bS[j], bG[j] + (K0));                         \
        asm volatile("cp.async.commit_group;");                                \
    } while (0)

    STAGE(0, 0);

    for (int it = 0; it < niter; it++) {
        asm volatile("cp.async.wait_group 0;");
        __syncthreads();
        if (it + 1 < niter) STAGE((it + 1) * 40, (it + 1) & 1);

        const float* As = smg + (it & 1) * GSTG;
        const float* Bs = As + 5632;
#pragma unroll
        for (int ks = 0; ks < 5; ks++) {
            const int kb = ks * 8;
            uint32_t afr[4][4];
#pragma unroll
            for (int mi = 0; mi < 4; mi++) {
                int m = wm * 64 + mi * 16 + g;
                afr[mi][0] = __float_as_uint(As[m * 44 + kb + tg]);
                afr[mi][1] = __float_as_uint(As[(m + 8) * 44 + kb + tg]);
                afr[mi][2] = __float_as_uint(As[m * 44 + kb + tg + 4]);
                afr[mi][3] = __float_as_uint(As[(m + 8) * 44 + kb + tg + 4]);
            }
            uint32_t bfr[5][2];
#pragma unroll
            for (int nj = 0; nj < 5; nj++) {
                int n = wn * 40 + nj * 8 + g;
                float2 bp = *(const float2*)&Bs[n * 44 + kb + tg * 2];  // pair-packed
                bfr[nj][0] = __float_as_uint(bp.x);
                bfr[nj][1] = __float_as_uint(bp.y);
            }
#pragma unroll
            for (int mi = 0; mi < 4; mi++)
#pragma unroll
                for (int nj = 0; nj < 5; nj++)
                    mma_tf32(acc[mi][nj], afr[mi], bfr[nj]);
        }
    }
#undef STAGE

#pragma unroll
    for (int mi = 0; mi < 4; mi++) {
        int mrow = m0 + wm * 64 + mi * 16 + g;
#pragma unroll
        for (int nj = 0; nj < 5; nj++) {
            int ncol = n0 + wn * 40 + nj * 8 + 2 * tg;
            float bx = bc[ncol], by = bc[ncol + 1];
            *(float2*)(d_g + (size_t)mrow * G16 + ncol) =
                make_float2(acc[mi][nj][0] + bx, acc[mi][nj][1] + by);
            *(float2*)(d_g + (size_t)(mrow + 8) * G16 + ncol) =
                make_float2(acc[mi][nj][2] + bx, acc[mi][nj][3] + by);
        }
    }
}

// ---------------- persistent tensor-core bidirectional LSTM (R12 proven) ---
// 100 blocks = 2 dir x 2 batch-halves x 25 u-slices. 128 thr (4 warps).
// Sync: per-lane REDG counters. d_h k-pair-packed. MUFU activations.
#define NDB 25

__global__ __launch_bounds__(128, 1)
void lstm_layer(const float* __restrict__ Whhf, const float* __restrict__ Whhb, int layer) {
    extern __shared__ float sm[];
    float* hs = sm;            // [64][212] = 13568 floats
    float* Wp = sm + 13568;    // [32][206] = 6592 floats

    const int tid = threadIdx.x;
    const int lane = tid & 31, w = tid >> 5;   // w in 0..3
    const int bx = blockIdx.x;
    const int dir = bx / (2 * NDB);
    const int mh  = (bx / NDB) & 1;
    const int us  = bx % NDB;
    const int u0  = us * 8;
    const float* Whh = dir ? Whhb : Whhf;
    float* out = layer ? d_rnn : d_x1;
    float* hbuf0 = d_h[layer][dir][0];
    float* hbuf1 = d_h[layer][dir][1];

    // pack W_hh slice, tf32, pair-packed for float2 B-fragment loads
    for (int i = tid; i < 32 * 200; i += 128) {
        int n = i / 200, p = i % 200;
        int k0 = p >> 3, r = p & 7, tg2 = r >> 1, c = r & 1;
        int k = k0 * 8 + tg2 + 4 * c;
        int grow = (n >> 3) * Hh + u0 + (n & 7);
        Wp[n * 206 + p] = to_tf32(Whh[(size_t)grow * Hh + k]);
    }
    __syncthreads();

    const int m0 = mh * 64 + w * 16;   // global batch base for this warp
    const int lr0 = w * 16;            // local hs row base
    const int g = lane >> 2, tg = lane & 3;
    unsigned* bar = d_barc[layer] + (((dir * 2 + mh) * 4 + w) * 32);
    const uint32_t hs_base = (uint32_t)__cvta_generic_to_shared(hs);

    // packed positions (within 8-group) for this lane's two hidden units
    const int pu0 = (((2 * tg) & 3) << 1) | ((2 * tg) >> 2);          // u = u0+2tg
    const int pu1 = (((2 * tg + 1) & 3) << 1) | ((2 * tg + 1) >> 2);  // u = u0+2tg+1

    float cst[4] = {0.f, 0.f, 0.f, 0.f};
    float hreg[4] = {0.f, 0.f, 0.f, 0.f};

    // prefetch gates + mask for step 0
    float2 gx[4][2];
    float mk0, mk1;
    {
        int t0 = dir ? Tt - 1 : 0;
#pragma unroll
        for (int j = 0; j < 4; j++) {
            gx[j][0] = *(const float2*)&d_g[(size_t)((m0 + g) * Tt + t0) * G16 +
                                            dir * 800 + j * 200 + u0 + 2 * tg];
            gx[j][1] = *(const float2*)&d_g[(size_t)((m0 + g + 8) * Tt + t0) * G16 +
                                            dir * 800 + j * 200 + u0 + 2 * tg];
        }
        mk0 = d_mt[t0 * Bsz + m0 + g];
        mk1 = d_mt[t0 * Bsz + m0 + g + 8];
    }

    for (int s = 0; s < Tt; s++) {
        const int t = dir ? (Tt - 1 - s) : s;
        const float* hcur = (s & 1) ? hbuf1 : hbuf0;
        float* hnxt = (s & 1) ? hbuf0 : hbuf1;

        // wait for all 25 blocks of this warp-group to finish step s-1
        if (s) {
            unsigned tgt = (unsigned)NDB * (unsigned)s;
            while (ld_acq(&bar[lane]) < tgt) {}
        }
        __syncwarp();

        // bulk-stage this warp's 16 batch rows of h_prev (L1-bypassed)
        for (int i = lane; i < 800; i += 32) {
            int r16 = i / 50, c4 = (i % 50) * 4;
            cp16(hs_base + (uint32_t)((lr0 + r16) * 212 + c4) * 4,
                 hcur + (size_t)(m0 + r16) * Hh + c4);
        }
        asm volatile("cp.async.commit_group;");
        asm volatile("cp.async.wait_group 0;");
        __syncwarp();

        float acc[4][4];
#pragma unroll
        for (int j = 0; j < 4; j++)
#pragma unroll
            for (int r = 0; r < 4; r++) acc[j][r] = 0.f;

#pragma unroll
        for (int ik = 0; ik < 25; ik++) {
            const int kb = ik * 8;
            uint32_t a[4];
            {
                float2 f0 = *(const float2*)&hs[(lr0 + g) * 212 + kb + tg * 2];      // packed
                float2 f1 = *(const float2*)&hs[(lr0 + g + 8) * 212 + kb + tg * 2];
                a[0] = __float_as_uint(f0.x);
                a[1] = __float_as_uint(f1.x);
                a[2] = __float_as_uint(f0.y);
                a[3] = __float_as_uint(f1.y);
            }
#pragma unroll
            for (int j = 0; j < 4; j++) {
                float2 bp = *(const float2*)&Wp[(j * 8 + g) * 206 + kb + tg * 2];
                uint32_t bb[2] = { __float_as_uint(bp.x), __float_as_uint(bp.y) };
                mma_tf32(acc[j], a, bb);
            }
        }

#pragma unroll
        for (int j = 0; j < 4; j++) {
            acc[j][0] += gx[j][0].x; acc[j][1] += gx[j][0].y;
            acc[j][2] += gx[j][1].x; acc[j][3] += gx[j][1].y;
        }

        // cell update in registers (MUFU.TANH path)
        float ho[4];
#pragma unroll
        for (int r = 0; r < 4; r++) {
            float m = (r >> 1) ? mk1 : mk0;
            float iv = sig_(acc[0][r]);
            float fv = sig_(acc[1][r]);
            float gv = tanh_(acc[2][r]);
            float ov = sig_(acc[3][r]);
            float cn = fv * cst[r] + iv * gv;
            float hn = ov * tanh_(cn);
            float hnew = m * hn + (1.f - m) * hreg[r];
            cst[r] = m * cn + (1.f - m) * cst[r];
            hreg[r] = hnew;
            ho[r] = m * hn;
        }

        // store h_next (tf32, k-pair-packed positions)
        hnxt[(size_t)(m0 + g) * Hh + u0 + pu0]     = to_tf32(hreg[0]);
        hnxt[(size_t)(m0 + g) * Hh + u0 + pu1]     = to_tf32(hreg[1]);
        hnxt[(size_t)(m0 + g + 8) * Hh + u0 + pu0] = to_tf32(hreg[2]);
        hnxt[(size_t)(m0 + g + 8) * Hh + u0 + pu1] = to_tf32(hreg[3]);

        // release: each lane orders its own stores (spread-address REDG)
        red_rel(&bar[lane]);

        // ---- tail (off other blocks' critical path) ----
        {
            float2 o0 = make_float2(layer ? ho[0] : to_tf32(ho[0]),
                                    layer ? ho[1] : to_tf32(ho[1]));
            float2 o1 = make_float2(layer ? ho[2] : to_tf32(ho[2]),
                                    layer ? ho[3] : to_tf32(ho[3]));
            *(float2*)&out[(size_t)((m0 + g) * Tt + t) * IN1 + dir * Hh + u0 + 2 * tg] = o0;
            *(float2*)&out[(size_t)((m0 + g + 8) * Tt + t) * IN1 + dir * Hh + u0 + 2 * tg] = o1;
        }
        if (layer && s == Tt - 1) {
            *(float2*)&d_hfin[dir][(m0 + g) * Hh + u0 + 2 * tg] =
                make_float2(hreg[0], hreg[1]);
            *(float2*)&d_hfin[dir][(m0 + g + 8) * Hh + u0 + 2 * tg] =
                make_float2(hreg[2], hreg[3]);
        }
        if (s < Tt - 1) {
            int tn = dir ? (Tt - 2 - s) : (s + 1);
#pragma unroll
            for (int j = 0; j < 4; j++) {
                gx[j][0] = *(const float2*)&d_g[(size_t)((m0 + g) * Tt + tn) * G16 +
                                                dir * 800 + j * 200 + u0 + 2 * tg];
                gx[j][1] = *(const float2*)&d_g[(size_t)((m0 + g + 8) * Tt + tn) * G16 +
                                                dir * 800 + j * 200 + u0 + 2 * tg];
            }
            mk0 = d_mt[tn * Bsz + m0 + g];
            mk1 = d_mt[tn * Bsz + m0 + g + 8];
        }
    }
}

// ---------------- fused pool + MLP head: span sums + 3x attention + classify
__global__ __launch_bounds__(256)
void pool_final_kernel(const int* __restrict__ masks, const int* __restrict__ subj,
                       const int* __restrict__ obj,
                       const float* __restrict__ wo_w, const float* __restrict__ wo_b,
                       const float* __restrict__ ws_w, const float* __restrict__ ws_b,
                       const float* __restrict__ wg_w, const float* __restrict__ wg_b,
                       const float* __restrict__ cls_w, const float* __restrict__ cls_b,
                       float* __restrict__ outp) {
    int b = blockIdx.x;
    __shared__ float ssel[Tt];       // reused as hv[] for the head
    __shared__ float osel[Tt];
    __shared__ float qv[3][IN1];     // queries, then reused as attention outputs
    __shared__ float ps[3][Tt];
    __shared__ float red[256];
    int tid = threadIdx.x, lane = tid & 31, w = tid >> 5;

    for (int t = tid; t < Tt; t += 256) {
        int m = masks[b * Tt + t];
        ssel[t] = (subj[b * Tt + t] + m == 0) ? 1.f : 0.f;
        osel[t] = (obj[b * Tt + t] + m == 0) ? 1.f : 0.f;
    }
    __syncthreads();

    // pass 1: span sums -> queries (+ glob_h gather)
    for (int f = tid; f < IN1; f += 256) {
        float ss = 0.f, os = 0.f;
        for (int t = 0; t < Tt; t++) {
            float v = d_rnn[(size_t)(b * Tt + t) * IN1 + f];
            ss += v * ssel[t];
            os += v * osel[t];
        }
        qv[0][f] = os;
        qv[1][f] = ss;
        qv[2][f] = (f < Hh) ? d_hfin[1][b * Hh + f] : d_hfin[0][b * Hh + f - Hh];
    }
    __syncthreads();

    // pass 2: scoring (warp per t, 3 dots per row read)
    for (int t = w; t < Tt; t += 8) {
        const float* row = d_rnn + (size_t)(b * Tt + t) * IN1;
        float s0 = 0.f, s1 = 0.f, s2 = 0.f;
        for (int k = lane; k < IN1; k += 32) {
            float v = row[k];
            s0 += qv[0][k] * v;
            s1 += qv[1][k] * v;
            s2 += qv[2][k] * v;
        }
        for (int o = 16; o; o >>= 1) {
            s0 += __shfl_down_sync(0xffffffffu, s0, o);
            s1 += __shfl_down_sync(0xffffffffu, s1, o);
            s2 += __shfl_down_sync(0xffffffffu, s2, o);
        }
        if (lane == 0) {
            ps[0][t] = s0 * 0.05f;
            ps[1][t] = s1 * 0.05f;
            ps[2][t] = s2 * 0.05f;
        }
    }
    __syncthreads();

    {
        bool pad = masks[b * Tt + tid] != 0;
        if (pad) { ps[0][tid] = -1e9f; ps[1][tid] = -1e9f; ps[2][tid] = -1e9f; }
    }
    __syncthreads();

    // pass 3: softmax per query
#pragma unroll
    for (int qi = 0; qi < 3; qi++) {
        float sc = ps[qi][tid];
        red[tid] = sc; __syncthreads();
        for (int o = 128; o; o >>= 1) { if (tid < o) red[tid] = fmaxf(red[tid], red[tid + o]); __syncthreads(); }
        float mx = red[0]; __syncthreads();
        float e = __expf(sc - mx);
        red[tid] = e; __syncthreads();
        for (int o = 128; o; o >>= 1) { if (tid < o) red[tid] += red[tid + o]; __syncthreads(); }
        float inv = 1.f / red[0];
        __syncthreads();
        ps[qi][tid] = e * inv;
        __syncthreads();
    }

    // pass 4: weighted accumulation -> store into qv (queries no longer needed)
    float av[3][2];
#pragma unroll
    for (int r = 0; r < 2; r++) { av[0][r] = av[1][r] = av[2][r] = 0.f; }
    for (int t = 0; t < Tt; t++) {
        float p0 = ps[0][t], p1 = ps[1][t], p2 = ps[2][t];
        const float* row = d_rnn + (size_t)(b * Tt + t) * IN1;
#pragma unroll
        for (int r = 0; r < 2; r++) {
            int f = tid + 256 * r;
            if (f < IN1) {
                float v = row[f];
                av[0][r] += p0 * v;
                av[1][r] += p1 * v;
                av[2][r] += p2 * v;
            }
        }
    }
    __syncthreads();
#pragma unroll
    for (int r = 0; r < 2; r++) {
        int f = tid + 256 * r;
        if (f < IN1) {
            qv[0][f] = av[0][r];
            qv[1][f] = av[1][r];
            qv[2][f] = av[2][r];
        }
    }
    __syncthreads();

    // ---- MLP head ----
    if (tid < Hh) {
        int j = tid;
        float a = wo_b[j] + ws_b[j] + wg_b[j];
        const float* wo = wo_w + (size_t)j * IN1;
        const float* ws = ws_w + (size_t)j * IN1;
        const float* wg = wg_w + (size_t)j * IN1;
        for (int k = 0; k < IN1; k++)
            a += qv[0][k] * wo[k] + qv[1][k] * ws[k] + qv[2][k] * wg[k];
        ssel[j] = fmaxf(a, 0.f);
    }
    __syncthreads();
    if (tid < 64) {
        int n = tid >> 5, l = tid & 31;
        float p = 0.f;
        for (int k = l; k < Hh; k += 32) p += ssel[k] * cls_w[n * Hh + k];
        for (int o = 16; o; o >>= 1) p += __shfl_down_sync(0xffffffffu, p, o);
        if (l == 0) outp[b * NCLASS + n] = p + cls_b[n];
    }
}

// ---------------- launcher ----------------
extern "C" void kernel_launch(void* const* d_in, const int* in_sizes, int n_in,
                              void* d_out, int out_size) {
    const int*   words    = (const int*)d_in[0];
    const int*   masks    = (const int*)d_in[1];
    const int*   pos      = (const int*)d_in[2];
    const int*   ner      = (const int*)d_in[3];
    const int*   subj_pos = (const int*)d_in[4];
    const int*   obj_pos  = (const int*)d_in[5];
    const float* emb_w    = (const float*)d_in[6];
    const float* pos_w    = (const float*)d_in[7];
    const float* ner_w    = (const float*)d_in[8];
    const float* w_ih_l0f = (const float*)d_in[9];
    const float* w_hh_l0f = (const float*)d_in[10];
    const float* b_l0f    = (const float*)d_in[11];
    const float* w_ih_l0b = (const float*)d_in[12];
    const float* w_hh_l0b = (const float*)d_in[13];
    const float* b_l0b    = (const float*)d_in[14];
    const float* w_ih_l1f = (const float*)d_in[15];
    const float* w_hh_l1f = (const float*)d_in[16];
    const float* b_l1f    = (const float*)d_in[17];
    const float* w_ih_l1b = (const float*)d_in[18];
    const float* w_hh_l1b = (const float*)d_in[19];
    const float* b_l1b    = (const float*)d_in[20];
    const float* wo_w     = (const float*)d_in[21];
    const float* wo_b     = (const float*)d_in[22];
    const float* ws_w     = (const float*)d_in[23];
    const float* ws_b     = (const float*)d_in[24];
    const float* wg_w     = (const float*)d_in[25];
    const float* wg_b     = (const float*)d_in[26];
    const float* cls_w    = (const float*)d_in[27];
    const float* cls_b    = (const float*)d_in[28];

    static const int GEMM_SMEM = 2 * GSTG * 4;   // 101376 B (2 blocks/SM)
    static const int LSTM_SMEM = 20160 * 4;      // 80640 B
    cudaFuncSetAttribute(gemm_tf32, cudaFuncAttributeMaxDynamicSharedMemorySize, GEMM_SMEM);
    cudaFuncSetAttribute(lstm_layer, cudaFuncAttributeMaxDynamicSharedMemorySize, LSTM_SMEM);

    dim3 ggrid(10, 256);   // N=1600/160, M=32768/128

    embedprep_kernel<<<(BT * 400 + 255) / 256, 256>>>(
        words, pos, ner, emb_w, pos_w, ner_w,
        w_ih_l0f, w_ih_l0b, b_l0f, b_l0b,
        w_ih_l1f, w_ih_l1b, b_l1f, b_l1b, masks);                                        // 0
    gemm_tf32<<<ggrid, 256, GEMM_SMEM>>>(0, 0, 9);    // K=360                            // 1
    lstm_layer<<<4 * NDB, 128, LSTM_SMEM>>>(w_hh_l0f, w_hh_l0b, 0);                       // 2
    gemm_tf32<<<ggrid, 256, GEMM_SMEM>>>(1, 1, 10);   // K=400                            // 3
    lstm_layer<<<4 * NDB, 128, LSTM_SMEM>>>(w_hh_l1f, w_hh_l1b, 1);                       // 4
    pool_final_kernel<<<Bsz, 256>>>(masks, subj_pos, obj_pos,
                                    wo_w, wo_b, ws_w, ws_b, wg_w, wg_b, cls_w, cls_b,
                                    (float*)d_out);                                       // 5
}